// round 12
// baseline (speedup 1.0000x reference)
#include <cuda_runtime.h>
#include <cstdint>

#define NN 50000
#define NE 800000
#define AST 136  // bf16 elems per SMEM row: 128 data + 8 pad (272B stride, 16B-aligned)

// Scratch (allocation-free rule: __device__ globals)
__device__ float g_agg[NN * 128];
__device__ float g_x1[NN * 128];
__device__ int g_is64;
__device__ int g_deg[NN];
__device__ int g_rowptr[NN + 1];
__device__ int g_epos[NE];
__device__ int g_esrc[NE];

// ======================= CSR build =======================
__global__ void detect_kernel(const int* __restrict__ w) {
    __shared__ int any;
    if (threadIdx.x == 0) any = 0;
    __syncthreads();
    int nz = 0;
    for (int k = threadIdx.x; k < 1024; k += blockDim.x) nz |= __ldg(w + 2 * k + 1);
    if (nz) any = 1;
    __syncthreads();
    if (threadIdx.x == 0) g_is64 = any ? 0 : 1;
}

__device__ __forceinline__ int load_dst(const void* ei_raw, int e) {
    if (g_is64) return (int)__ldg((const long long*)ei_raw + NE + e);
    return __ldg((const int*)ei_raw + NE + e);
}
__device__ __forceinline__ int load_src(const void* ei_raw, int e) {
    if (g_is64) return (int)__ldg((const long long*)ei_raw + e);
    return __ldg((const int*)ei_raw + e);
}

// Pass 1: histogram + record each edge's slot within its destination bucket
__global__ void hist_kernel(const void* __restrict__ ei_raw) {
    int e = blockIdx.x * blockDim.x + threadIdx.x;
    if (e < NE) {
        int dst = load_dst(ei_raw, e);
        g_epos[e] = atomicAdd(&g_deg[dst], 1);
    }
}

// single-block exclusive scan: rowptr from deg
__global__ void scan_kernel() {
    __shared__ int part[1024];
    const int tid = threadIdx.x;
    const int CH = (NN + 1023) / 1024;  // 49
    int base = tid * CH;
    int s = 0;
#pragma unroll 4
    for (int i = 0; i < CH; i++) {
        int idx = base + i;
        if (idx < NN) s += g_deg[idx];
    }
    part[tid] = s;
    __syncthreads();
    for (int off = 1; off < 1024; off <<= 1) {
        int t = (tid >= off) ? part[tid - off] : 0;
        __syncthreads();
        part[tid] += t;
        __syncthreads();
    }
    int run = part[tid] - s;
    for (int i = 0; i < CH; i++) {
        int idx = base + i;
        if (idx < NN) {
            g_rowptr[idx] = run;
            run += g_deg[idx];
        }
    }
    if (tid == 0) g_rowptr[NN] = NE;
}

// Pass 2: atomic-free scatter of src indices into CSR order
__global__ void fill_kernel(const void* __restrict__ ei_raw) {
    int e = blockIdx.x * blockDim.x + threadIdx.x;
    if (e < NE) {
        int src = load_src(ei_raw, e);
        int dst = load_dst(ei_raw, e);
        g_esrc[__ldg(g_rowptr + dst) + g_epos[e]] = src;
    }
}

// ======================= CSR aggregation =======================
__global__ void agg_kernel(const float* __restrict__ x,
                           const float* __restrict__ eps,
                           float* __restrict__ agg) {
    int node = blockIdx.x * (blockDim.x >> 5) + (threadIdx.x >> 5);
    if (node >= NN) return;
    int lane = threadIdx.x & 31;
    float s = 1.0f + __ldg(eps);
    int beg = __ldg(g_rowptr + node), end = __ldg(g_rowptr + node + 1);

    float4 a = __ldg((const float4*)(x + (size_t)node * 128) + lane);
    float4 acc = make_float4(s * a.x, s * a.y, s * a.z, s * a.w);

    int j = beg;
    for (; j + 4 <= end; j += 4) {
        int s0 = __ldg(g_esrc + j), s1 = __ldg(g_esrc + j + 1);
        int s2 = __ldg(g_esrc + j + 2), s3 = __ldg(g_esrc + j + 3);
        float4 v0 = __ldg((const float4*)(x + (size_t)s0 * 128) + lane);
        float4 v1 = __ldg((const float4*)(x + (size_t)s1 * 128) + lane);
        float4 v2 = __ldg((const float4*)(x + (size_t)s2 * 128) + lane);
        float4 v3 = __ldg((const float4*)(x + (size_t)s3 * 128) + lane);
        acc.x += v0.x + v1.x; acc.y += v0.y + v1.y;
        acc.z += v0.z + v1.z; acc.w += v0.w + v1.w;
        acc.x += v2.x + v3.x; acc.y += v2.y + v3.y;
        acc.z += v2.z + v3.z; acc.w += v2.w + v3.w;
    }
    for (; j < end; j++) {
        int s0 = __ldg(g_esrc + j);
        float4 v = __ldg((const float4*)(x + (size_t)s0 * 128) + lane);
        acc.x += v.x; acc.y += v.y; acc.z += v.z; acc.w += v.w;
    }
    ((float4*)(agg + (size_t)node * 128))[lane] = acc;
}

// ===================== tensor-core MLP (mma.sync bf16 hi/lo split) =====================
#define TBUF (128 * AST * 2)   // 34816 B per 128x128 bf16 buffer
#define OB_W1H 0
#define OB_W1L (OB_W1H + TBUF)
#define OB_W2H (OB_W1L + TBUF)
#define OB_W2L (OB_W2H + TBUF)
#define OB_ATH (OB_W2L + TBUF)
#define OB_ATL (OB_ATH + TBUF)
#define OB_BA  (OB_ATL + TBUF)
#define OB_BB  (OB_BA + 512)
#define MLP_SMEM (OB_BB + 512)   // 209920 B

__device__ __forceinline__ uint32_t cvta_s(const void* p) {
    uint32_t r;
    asm("{ .reg .u64 t; cvta.to.shared.u64 t, %1; cvt.u32.u64 %0, t; }" : "=r"(r) : "l"(p));
    return r;
}
__device__ __forceinline__ uint32_t bfpack(float a, float b) {
    uint32_t r;
    asm("cvt.rn.bf16x2.f32 %0, %1, %2;" : "=r"(r) : "f"(b), "f"(a));
    return r;
}
__device__ __forceinline__ void split2(float a, float b, uint32_t& hi, uint32_t& lo) {
    hi = bfpack(a, b);
    float ah = __uint_as_float(hi << 16);
    float bh = __uint_as_float(hi & 0xFFFF0000u);
    lo = bfpack(a - ah, b - bh);
}
__device__ __forceinline__ void split4(float4 v, uint2& hi, uint2& lo) {
    split2(v.x, v.y, hi.x, lo.x);
    split2(v.z, v.w, hi.y, lo.y);
}

__device__ __forceinline__ void ldsm_x4(uint32_t r[4], uint32_t a) {
    asm volatile("ldmatrix.sync.aligned.m8n8.x4.shared.b16 {%0,%1,%2,%3}, [%4];"
                 : "=r"(r[0]), "=r"(r[1]), "=r"(r[2]), "=r"(r[3]) : "r"(a));
}
__device__ __forceinline__ void ldsm_x2(uint32_t r[2], uint32_t a) {
    asm volatile("ldmatrix.sync.aligned.m8n8.x2.shared.b16 {%0,%1}, [%2];"
                 : "=r"(r[0]), "=r"(r[1]) : "r"(a));
}
__device__ __forceinline__ void mma16816(float c[4], const uint32_t a[4], const uint32_t b[2]) {
    asm volatile("mma.sync.aligned.m16n8k16.row.col.f32.bf16.bf16.f32 "
                 "{%0,%1,%2,%3},{%4,%5,%6,%7},{%8,%9},{%0,%1,%2,%3};"
                 : "+f"(c[0]), "+f"(c[1]), "+f"(c[2]), "+f"(c[3])
                 : "r"(a[0]), "r"(a[1]), "r"(a[2]), "r"(a[3]), "r"(b[0]), "r"(b[1]));
}

// warp covers A rows r_base..+31 (t=0,1), W cols c_base..+63
__device__ __forceinline__ void mma_gemm(uint32_t sb, int offAH, int offAL, int offWH, int offWL,
                                         int lane, int r_base, int c_base, float c[2][8][4]) {
#pragma unroll
    for (int t = 0; t < 2; t++)
#pragma unroll
        for (int n = 0; n < 8; n++)
#pragma unroll
            for (int q = 0; q < 4; q++) c[t][n][q] = 0.f;

    const int arow = lane & 15, acol = (lane >> 4) << 3;
    const int bwrow = lane & 7, bcol = ((lane >> 3) & 1) << 3;
#pragma unroll
    for (int kt = 0; kt < 128; kt += 16) {
        uint32_t a[2][2][4];
#pragma unroll
        for (int t = 0; t < 2; t++) {
            uint32_t bo = (uint32_t)(((r_base + t * 16 + arow) * AST + kt + acol) * 2);
            ldsm_x4(a[t][0], sb + offAH + bo);
            ldsm_x4(a[t][1], sb + offAL + bo);
        }
#pragma unroll
        for (int n = 0; n < 8; n++) {
            uint32_t bo = (uint32_t)(((c_base + n * 8 + bwrow) * AST + kt + bcol) * 2);
            uint32_t bh[2], bl[2];
            ldsm_x2(bh, sb + offWH + bo);
            ldsm_x2(bl, sb + offWL + bo);
#pragma unroll
            for (int t = 0; t < 2; t++) {
                mma16816(c[t][n], a[t][0], bh);  // hi*hi
                mma16816(c[t][n], a[t][0], bl);  // hi*lo
                mma16816(c[t][n], a[t][1], bh);  // lo*hi
            }
        }
    }
}

template <bool RELU_OUT>
__global__ void __launch_bounds__(256, 1)
mlp_kernel(const float* __restrict__ H,
           const float* __restrict__ wA, const float* __restrict__ bA,
           const float* __restrict__ wB, const float* __restrict__ bB,
           float* __restrict__ out) {
    extern __shared__ char smem[];
    const uint32_t sb = cvta_s(smem);
    const int tid = threadIdx.x, lane = tid & 31, wid = tid >> 5;
    const int r_base = (wid & 3) * 32, c_base = (wid >> 2) * 64;
    float* ba = (float*)(smem + OB_BA);
    float* bb = (float*)(smem + OB_BB);

    // Weights -> bf16 hi/lo in SMEM (row-major [c][k], stride AST)
    for (int i = tid; i < 4096; i += 256) {
        int row = i >> 5, col = (i & 31) << 2;
        uint2 hi, lo;
        float4 v = __ldg((const float4*)wA + i);
        split4(v, hi, lo);
        *(uint2*)(smem + OB_W1H + (row * AST + col) * 2) = hi;
        *(uint2*)(smem + OB_W1L + (row * AST + col) * 2) = lo;
        v = __ldg((const float4*)wB + i);
        split4(v, hi, lo);
        *(uint2*)(smem + OB_W2H + (row * AST + col) * 2) = hi;
        *(uint2*)(smem + OB_W2L + (row * AST + col) * 2) = lo;
    }
    if (tid < 128) {
        ba[tid] = __ldg(bA + tid);
        bb[tid] = __ldg(bB + tid);
    }

    const int NT = (NN + 127) / 128;  // 391 tiles
    for (int tile = blockIdx.x; tile < NT; tile += gridDim.x) {
        int rowBase = tile << 7;
        // fill A tile (bf16 hi/lo)
        for (int i = tid; i < 4096; i += 256) {
            int r = i >> 5, col = (i & 31) << 2;
            int gr = rowBase + r;
            float4 v = make_float4(0.f, 0.f, 0.f, 0.f);
            if (gr < NN) v = __ldg((const float4*)H + (size_t)gr * 32 + (i & 31));
            uint2 hi, lo;
            split4(v, hi, lo);
            *(uint2*)(smem + OB_ATH + (r * AST + col) * 2) = hi;
            *(uint2*)(smem + OB_ATL + (r * AST + col) * 2) = lo;
        }
        __syncthreads();

        float c[2][8][4];
        mma_gemm(sb, OB_ATH, OB_ATL, OB_W1H, OB_W1L, lane, r_base, c_base, c);
        __syncthreads();  // all warps done reading A before T overwrites it

        // epilogue1: bias + relu -> T (bf16 hi/lo, same buffers)
#pragma unroll
        for (int t = 0; t < 2; t++)
#pragma unroll
            for (int n = 0; n < 8; n++) {
                int r0 = r_base + t * 16 + (lane >> 2);
                int col = c_base + n * 8 + ((lane & 3) << 1);
                float b0 = ba[col], b1 = ba[col + 1];
                float v0 = fmaxf(c[t][n][0] + b0, 0.f);
                float v1 = fmaxf(c[t][n][1] + b1, 0.f);
                uint32_t h, l;
                split2(v0, v1, h, l);
                *(uint32_t*)(smem + OB_ATH + (r0 * AST + col) * 2) = h;
                *(uint32_t*)(smem + OB_ATL + (r0 * AST + col) * 2) = l;
                float v2 = fmaxf(c[t][n][2] + b0, 0.f);
                float v3 = fmaxf(c[t][n][3] + b1, 0.f);
                split2(v2, v3, h, l);
                *(uint32_t*)(smem + OB_ATH + ((r0 + 8) * AST + col) * 2) = h;
                *(uint32_t*)(smem + OB_ATL + ((r0 + 8) * AST + col) * 2) = l;
            }
        __syncthreads();

        mma_gemm(sb, OB_ATH, OB_ATL, OB_W2H, OB_W2L, lane, r_base, c_base, c);

        // epilogue2: bias [+relu] -> global
#pragma unroll
        for (int t = 0; t < 2; t++)
#pragma unroll
            for (int n = 0; n < 8; n++) {
                int r0 = r_base + t * 16 + (lane >> 2);
                int col = c_base + n * 8 + ((lane & 3) << 1);
                float b0 = bb[col], b1 = bb[col + 1];
                int gr = rowBase + r0;
                if (gr < NN) {
                    float v0 = c[t][n][0] + b0, v1 = c[t][n][1] + b1;
                    if (RELU_OUT) { v0 = fmaxf(v0, 0.f); v1 = fmaxf(v1, 0.f); }
                    *(float2*)(out + (size_t)gr * 128 + col) = make_float2(v0, v1);
                }
                if (gr + 8 < NN) {
                    float v2 = c[t][n][2] + b0, v3 = c[t][n][3] + b1;
                    if (RELU_OUT) { v2 = fmaxf(v2, 0.f); v3 = fmaxf(v3, 0.f); }
                    *(float2*)(out + (size_t)(gr + 8) * 128 + col) = make_float2(v2, v3);
                }
            }
        __syncthreads();  // before next tile's A fill
    }
}

extern "C" void kernel_launch(void* const* d_in, const int* in_sizes, int n_in,
                              void* d_out, int out_size) {
    const float* features = (const float*)d_in[0];
    const void*  ei       = d_in[1];
    const float* w1a      = (const float*)d_in[2];
    const float* b1a      = (const float*)d_in[3];
    const float* w1b      = (const float*)d_in[4];
    const float* b1b      = (const float*)d_in[5];
    const float* eps1     = (const float*)d_in[6];
    const float* w2a      = (const float*)d_in[7];
    const float* b2a      = (const float*)d_in[8];
    const float* w2b      = (const float*)d_in[9];
    const float* b2b      = (const float*)d_in[10];
    const float* eps2     = (const float*)d_in[11];
    float* out = (float*)d_out;

    float *agg, *x1;
    cudaGetSymbolAddress((void**)&agg, g_agg);
    cudaGetSymbolAddress((void**)&x1, g_x1);
    int* degp;
    cudaGetSymbolAddress((void**)&degp, g_deg);

    cudaFuncSetAttribute(mlp_kernel<true>,
                         cudaFuncAttributeMaxDynamicSharedMemorySize, MLP_SMEM);
    cudaFuncSetAttribute(mlp_kernel<false>,
                         cudaFuncAttributeMaxDynamicSharedMemorySize, MLP_SMEM);

    // CSR build (once per call, reused by both layers)
    cudaMemsetAsync(degp, 0, NN * sizeof(int));
    detect_kernel<<<1, 256>>>((const int*)ei);
    hist_kernel<<<(NE + 511) / 512, 512>>>(ei);
    scan_kernel<<<1, 1024>>>();
    fill_kernel<<<(NE + 511) / 512, 512>>>(ei);

    // Layer 1
    agg_kernel<<<(NN * 32 + 255) / 256, 256>>>(features, eps1, agg);
    mlp_kernel<true><<<148, 256, MLP_SMEM>>>(agg, w1a, b1a, w1b, b1b, x1);

    // Layer 2
    agg_kernel<<<(NN * 32 + 255) / 256, 256>>>(x1, eps2, agg);
    mlp_kernel<false><<<148, 256, MLP_SMEM>>>(agg, w2a, b2a, w2b, b2b, out);
}

// round 13
// speedup vs baseline: 1.2640x; 1.2640x over previous
#include <cuda_runtime.h>
#include <cstdint>

#define NN 50000
#define NE 800000
#define AST 136  // bf16 elems per SMEM row: 128 data + 8 pad (272B stride, 16B-aligned)

// Scratch (allocation-free rule: __device__ globals)
__device__ float g_agg[NN * 128];
__device__ float g_x1[NN * 128];
__device__ int g_is64;
__device__ int g_deg[NN];
__device__ int g_rowptr[NN + 1];
__device__ int g_cur[NN];
__device__ int g_esrc[NE];

// ======================= CSR build (R10-proven form) =======================
__global__ void detect_and_zero_kernel(const int* __restrict__ w) {
    int i = blockIdx.x * blockDim.x + threadIdx.x;
    for (int k = i; k < NN; k += gridDim.x * blockDim.x) g_deg[k] = 0;
    if (blockIdx.x == 0) {
        __shared__ int any;
        if (threadIdx.x == 0) any = 0;
        __syncthreads();
        int nz = 0;
        for (int k = threadIdx.x; k < 1024; k += blockDim.x) nz |= __ldg(w + 2 * k + 1);
        if (nz) any = 1;
        __syncthreads();
        if (threadIdx.x == 0) g_is64 = any ? 0 : 1;
    }
}

__device__ __forceinline__ int load_dst(const void* ei_raw, int e) {
    if (g_is64) return (int)__ldg((const long long*)ei_raw + NE + e);
    return __ldg((const int*)ei_raw + NE + e);
}
__device__ __forceinline__ void load_edge(const void* ei_raw, int e, int& src, int& dst) {
    if (g_is64) {
        const long long* ei = (const long long*)ei_raw;
        src = (int)__ldg(ei + e);
        dst = (int)__ldg(ei + NE + e);
    } else {
        const int* ei = (const int*)ei_raw;
        src = __ldg(ei + e);
        dst = __ldg(ei + NE + e);
    }
}

// result unused -> compiles to REDG (no-return), fast under contention
__global__ void hist_kernel(const void* __restrict__ ei_raw) {
    int e = blockIdx.x * blockDim.x + threadIdx.x;
    if (e < NE) atomicAdd(&g_deg[load_dst(ei_raw, e)], 1);
}

__global__ void scan_kernel() {
    __shared__ int part[1024];
    const int tid = threadIdx.x;
    const int CH = (NN + 1023) / 1024;  // 49
    int base = tid * CH;
    int s = 0;
#pragma unroll 4
    for (int i = 0; i < CH; i++) {
        int idx = base + i;
        if (idx < NN) s += g_deg[idx];
    }
    part[tid] = s;
    __syncthreads();
    for (int off = 1; off < 1024; off <<= 1) {
        int t = (tid >= off) ? part[tid - off] : 0;
        __syncthreads();
        part[tid] += t;
        __syncthreads();
    }
    int run = part[tid] - s;
    for (int i = 0; i < CH; i++) {
        int idx = base + i;
        if (idx < NN) {
            g_rowptr[idx] = run;
            g_cur[idx] = run;
            run += g_deg[idx];
        }
    }
    if (tid == 0) g_rowptr[NN] = NE;
}

__global__ void fill_kernel(const void* __restrict__ ei_raw) {
    int e = blockIdx.x * blockDim.x + threadIdx.x;
    if (e < NE) {
        int src, dst;
        load_edge(ei_raw, e, src, dst);
        int p = atomicAdd(&g_cur[dst], 1);
        g_esrc[p] = src;
    }
}

// ======================= CSR aggregation =======================
__global__ void agg_kernel(const float* __restrict__ x,
                           const float* __restrict__ eps,
                           float* __restrict__ agg) {
    int node = blockIdx.x * (blockDim.x >> 5) + (threadIdx.x >> 5);
    if (node >= NN) return;
    int lane = threadIdx.x & 31;
    float s = 1.0f + __ldg(eps);
    int beg = __ldg(g_rowptr + node), end = __ldg(g_rowptr + node + 1);

    float4 a = __ldg((const float4*)(x + (size_t)node * 128) + lane);
    float4 acc = make_float4(s * a.x, s * a.y, s * a.z, s * a.w);

    int j = beg;
    for (; j + 4 <= end; j += 4) {
        int s0 = __ldg(g_esrc + j), s1 = __ldg(g_esrc + j + 1);
        int s2 = __ldg(g_esrc + j + 2), s3 = __ldg(g_esrc + j + 3);
        float4 v0 = __ldg((const float4*)(x + (size_t)s0 * 128) + lane);
        float4 v1 = __ldg((const float4*)(x + (size_t)s1 * 128) + lane);
        float4 v2 = __ldg((const float4*)(x + (size_t)s2 * 128) + lane);
        float4 v3 = __ldg((const float4*)(x + (size_t)s3 * 128) + lane);
        acc.x += v0.x + v1.x; acc.y += v0.y + v1.y;
        acc.z += v0.z + v1.z; acc.w += v0.w + v1.w;
        acc.x += v2.x + v3.x; acc.y += v2.y + v3.y;
        acc.z += v2.z + v3.z; acc.w += v2.w + v3.w;
    }
    for (; j < end; j++) {
        int s0 = __ldg(g_esrc + j);
        float4 v = __ldg((const float4*)(x + (size_t)s0 * 128) + lane);
        acc.x += v.x; acc.y += v.y; acc.z += v.z; acc.w += v.w;
    }
    ((float4*)(agg + (size_t)node * 128))[lane] = acc;
}

// ===================== tensor-core MLP: register-resident T =====================
// 8 warps; warp owns A rows r_base..r_base+15 and ALL 128 output cols.
// GEMM1 C-fragments == GEMM2 A-fragments -> no SMEM round-trip for T.
#define TBUF (128 * AST * 2)   // 34816 B per 128x128 bf16 buffer
#define OB_W1H 0
#define OB_W1L (OB_W1H + TBUF)
#define OB_W2H (OB_W1L + TBUF)
#define OB_W2L (OB_W2H + TBUF)
#define OB_ATH (OB_W2L + TBUF)
#define OB_ATL (OB_ATH + TBUF)
#define OB_BA  (OB_ATL + TBUF)
#define OB_BB  (OB_BA + 512)
#define MLP_SMEM (OB_BB + 512)   // 209920 B

__device__ __forceinline__ uint32_t cvta_s(const void* p) {
    uint32_t r;
    asm("{ .reg .u64 t; cvta.to.shared.u64 t, %1; cvt.u32.u64 %0, t; }" : "=r"(r) : "l"(p));
    return r;
}
__device__ __forceinline__ uint32_t bfpack(float a, float b) {
    uint32_t r;
    asm("cvt.rn.bf16x2.f32 %0, %1, %2;" : "=r"(r) : "f"(b), "f"(a));
    return r;
}
__device__ __forceinline__ void split2(float a, float b, uint32_t& hi, uint32_t& lo) {
    hi = bfpack(a, b);
    float ah = __uint_as_float(hi << 16);
    float bh = __uint_as_float(hi & 0xFFFF0000u);
    lo = bfpack(a - ah, b - bh);
}
__device__ __forceinline__ void split4(float4 v, uint2& hi, uint2& lo) {
    split2(v.x, v.y, hi.x, lo.x);
    split2(v.z, v.w, hi.y, lo.y);
}

__device__ __forceinline__ void ldsm_x4(uint32_t r[4], uint32_t a) {
    asm volatile("ldmatrix.sync.aligned.m8n8.x4.shared.b16 {%0,%1,%2,%3}, [%4];"
                 : "=r"(r[0]), "=r"(r[1]), "=r"(r[2]), "=r"(r[3]) : "r"(a));
}
__device__ __forceinline__ void ldsm_x2(uint32_t r[2], uint32_t a) {
    asm volatile("ldmatrix.sync.aligned.m8n8.x2.shared.b16 {%0,%1}, [%2];"
                 : "=r"(r[0]), "=r"(r[1]) : "r"(a));
}
__device__ __forceinline__ void mma16816(float c[4], const uint32_t a[4], const uint32_t b[2]) {
    asm volatile("mma.sync.aligned.m16n8k16.row.col.f32.bf16.bf16.f32 "
                 "{%0,%1,%2,%3},{%4,%5,%6,%7},{%8,%9},{%0,%1,%2,%3};"
                 : "+f"(c[0]), "+f"(c[1]), "+f"(c[2]), "+f"(c[3])
                 : "r"(a[0]), "r"(a[1]), "r"(a[2]), "r"(a[3]), "r"(b[0]), "r"(b[1]));
}

template <bool RELU_OUT>
__global__ void __launch_bounds__(256, 1)
mlp_kernel(const float* __restrict__ H,
           const float* __restrict__ wA, const float* __restrict__ bA,
           const float* __restrict__ wB, const float* __restrict__ bB,
           float* __restrict__ out) {
    extern __shared__ char smem[];
    const uint32_t sb = cvta_s(smem);
    const int tid = threadIdx.x, lane = tid & 31, wid = tid >> 5;
    const int r_base = wid * 16;   // warp's 16-row band; all 128 cols
    float* ba = (float*)(smem + OB_BA);
    float* bb = (float*)(smem + OB_BB);

    // Weights -> bf16 hi/lo in SMEM (row-major [c][k], stride AST)
    for (int i = tid; i < 4096; i += 256) {
        int row = i >> 5, col = (i & 31) << 2;
        uint2 hi, lo;
        float4 v = __ldg((const float4*)wA + i);
        split4(v, hi, lo);
        *(uint2*)(smem + OB_W1H + (row * AST + col) * 2) = hi;
        *(uint2*)(smem + OB_W1L + (row * AST + col) * 2) = lo;
        v = __ldg((const float4*)wB + i);
        split4(v, hi, lo);
        *(uint2*)(smem + OB_W2H + (row * AST + col) * 2) = hi;
        *(uint2*)(smem + OB_W2L + (row * AST + col) * 2) = lo;
    }
    if (tid < 128) {
        ba[tid] = __ldg(bA + tid);
        bb[tid] = __ldg(bB + tid);
    }

    const int arow = lane & 15, acol = (lane >> 4) << 3;
    const int bwrow = lane & 7, bcol = ((lane >> 3) & 1) << 3;
    const int NT = (NN + 127) / 128;  // 391 tiles

    for (int tile = blockIdx.x; tile < NT; tile += gridDim.x) {
        int rowBase = tile << 7;
        // ---- fill A tile (bf16 hi/lo) ----
        for (int i = tid; i < 4096; i += 256) {
            int r = i >> 5, col = (i & 31) << 2;
            int gr = rowBase + r;
            float4 v = make_float4(0.f, 0.f, 0.f, 0.f);
            if (gr < NN) v = __ldg((const float4*)H + (size_t)gr * 32 + (i & 31));
            uint2 hi, lo;
            split4(v, hi, lo);
            *(uint2*)(smem + OB_ATH + (r * AST + col) * 2) = hi;
            *(uint2*)(smem + OB_ATL + (r * AST + col) * 2) = lo;
        }
        __syncthreads();

        // ---- GEMM1: c1[n] over all 16 col-groups ----
        float c1[16][4];
#pragma unroll
        for (int n = 0; n < 16; n++)
#pragma unroll
            for (int q = 0; q < 4; q++) c1[n][q] = 0.f;
#pragma unroll
        for (int kt = 0; kt < 128; kt += 16) {
            uint32_t ah[4], al[4];
            uint32_t bo = (uint32_t)(((r_base + arow) * AST + kt + acol) * 2);
            ldsm_x4(ah, sb + OB_ATH + bo);
            ldsm_x4(al, sb + OB_ATL + bo);
#pragma unroll
            for (int n = 0; n < 16; n++) {
                uint32_t wo = (uint32_t)(((n * 8 + bwrow) * AST + kt + bcol) * 2);
                uint32_t bh[2], bl[2];
                ldsm_x2(bh, sb + OB_W1H + wo);
                ldsm_x2(bl, sb + OB_W1L + wo);
                mma16816(c1[n], ah, bh);
                mma16816(c1[n], ah, bl);
                mma16816(c1[n], al, bh);
            }
        }

        // ---- epilogue1 in registers: bias+relu, split to bf16 A-fragments ----
        // tah/tal[n][0] = rows (lane/4), tah[n][1] = rows (lane/4+8); cols n*8+(lane%4)*2
        uint32_t tah[16][2], tal[16][2];
#pragma unroll
        for (int n = 0; n < 16; n++) {
            int col = n * 8 + ((lane & 3) << 1);
            float b0 = ba[col], b1 = ba[col + 1];
            float v0 = fmaxf(c1[n][0] + b0, 0.f);
            float v1 = fmaxf(c1[n][1] + b1, 0.f);
            float v2 = fmaxf(c1[n][2] + b0, 0.f);
            float v3 = fmaxf(c1[n][3] + b1, 0.f);
            split2(v0, v1, tah[n][0], tal[n][0]);
            split2(v2, v3, tah[n][1], tal[n][1]);
        }

        // ---- GEMM2: A-fragments from registers, W2 from SMEM ----
        float c2[16][4];
#pragma unroll
        for (int n = 0; n < 16; n++)
#pragma unroll
            for (int q = 0; q < 4; q++) c2[n][q] = 0.f;
#pragma unroll
        for (int kt = 0; kt < 8; kt++) {
            // A-frag for k-chunk 16*kt: a0,a1 from n=2kt (k..k+7); a2,a3 from n=2kt+1 (k+8..k+15)
            uint32_t ah[4] = { tah[2 * kt][0], tah[2 * kt][1], tah[2 * kt + 1][0], tah[2 * kt + 1][1] };
            uint32_t al[4] = { tal[2 * kt][0], tal[2 * kt][1], tal[2 * kt + 1][0], tal[2 * kt + 1][1] };
#pragma unroll
            for (int n = 0; n < 16; n++) {
                uint32_t wo = (uint32_t)(((n * 8 + bwrow) * AST + kt * 16 + bcol) * 2);
                uint32_t bh[2], bl[2];
                ldsm_x2(bh, sb + OB_W2H + wo);
                ldsm_x2(bl, sb + OB_W2L + wo);
                mma16816(c2[n], ah, bh);
                mma16816(c2[n], ah, bl);
                mma16816(c2[n], al, bh);
            }
        }

        // ---- epilogue2: bias [+relu] -> global ----
        int gr0 = rowBase + r_base + (lane >> 2);
#pragma unroll
        for (int n = 0; n < 16; n++) {
            int col = n * 8 + ((lane & 3) << 1);
            float b0 = bb[col], b1 = bb[col + 1];
            if (gr0 < NN) {
                float v0 = c2[n][0] + b0, v1 = c2[n][1] + b1;
                if (RELU_OUT) { v0 = fmaxf(v0, 0.f); v1 = fmaxf(v1, 0.f); }
                *(float2*)(out + (size_t)gr0 * 128 + col) = make_float2(v0, v1);
            }
            if (gr0 + 8 < NN) {
                float v2 = c2[n][2] + b0, v3 = c2[n][3] + b1;
                if (RELU_OUT) { v2 = fmaxf(v2, 0.f); v3 = fmaxf(v3, 0.f); }
                *(float2*)(out + (size_t)(gr0 + 8) * 128 + col) = make_float2(v2, v3);
            }
        }
        __syncthreads();  // before next tile's A fill overwrites A smem
    }
}

extern "C" void kernel_launch(void* const* d_in, const int* in_sizes, int n_in,
                              void* d_out, int out_size) {
    const float* features = (const float*)d_in[0];
    const void*  ei       = d_in[1];
    const float* w1a      = (const float*)d_in[2];
    const float* b1a      = (const float*)d_in[3];
    const float* w1b      = (const float*)d_in[4];
    const float* b1b      = (const float*)d_in[5];
    const float* eps1     = (const float*)d_in[6];
    const float* w2a      = (const float*)d_in[7];
    const float* b2a      = (const float*)d_in[8];
    const float* w2b      = (const float*)d_in[9];
    const float* b2b      = (const float*)d_in[10];
    const float* eps2     = (const float*)d_in[11];
    float* out = (float*)d_out;

    float *agg, *x1;
    cudaGetSymbolAddress((void**)&agg, g_agg);
    cudaGetSymbolAddress((void**)&x1, g_x1);

    cudaFuncSetAttribute(mlp_kernel<true>,
                         cudaFuncAttributeMaxDynamicSharedMemorySize, MLP_SMEM);
    cudaFuncSetAttribute(mlp_kernel<false>,
                         cudaFuncAttributeMaxDynamicSharedMemorySize, MLP_SMEM);

    // CSR build (once per call, reused by both layers)
    detect_and_zero_kernel<<<64, 256>>>((const int*)ei);
    hist_kernel<<<(NE + 511) / 512, 512>>>(ei);
    scan_kernel<<<1, 1024>>>();
    fill_kernel<<<(NE + 511) / 512, 512>>>(ei);

    // Layer 1
    agg_kernel<<<(NN * 32 + 255) / 256, 256>>>(features, eps1, agg);
    mlp_kernel<true><<<148, 256, MLP_SMEM>>>(agg, w1a, b1a, w1b, b1b, x1);

    // Layer 2
    agg_kernel<<<(NN * 32 + 255) / 256, 256>>>(x1, eps2, agg);
    mlp_kernel<false><<<148, 256, MLP_SMEM>>>(agg, w2a, b2a, w2b, b2b, out);
}

// round 14
// speedup vs baseline: 1.2987x; 1.0275x over previous
#include <cuda_runtime.h>
#include <cstdint>

#define NN 50000
#define NE 800000
#define AST 136         // bf16 elems per row: 128 data + 8 pad (272B stride)
#define NT 391          // ceil(NN/128)
#define TBUF (128 * AST * 2)   // 34816 B per 128x128 bf16 plane

// Scratch (allocation-free rule: __device__ globals)
__device__ char g_aggH[NT * TBUF];   // bf16 hi plane, tile-blocked AST layout
__device__ char g_aggL[NT * TBUF];   // bf16 lo plane
__device__ float g_x1[NN * 128];
__device__ int g_is64;
__device__ int g_deg[NN];
__device__ int g_rowptr[NN + 1];
__device__ int g_cur[NN];
__device__ int g_esrc[NE];

// ======================= CSR build =======================
__global__ void detect_kernel(const int* __restrict__ w) {
    __shared__ int any;
    if (threadIdx.x == 0) any = 0;
    __syncthreads();
    int nz = 0;
    for (int k = threadIdx.x; k < 1024; k += blockDim.x) nz |= __ldg(w + 2 * k + 1);
    if (nz) any = 1;
    __syncthreads();
    if (threadIdx.x == 0) g_is64 = any ? 0 : 1;
}

__device__ __forceinline__ int load_dst(const void* ei_raw, int e) {
    if (g_is64) return (int)__ldg((const long long*)ei_raw + NE + e);
    return __ldg((const int*)ei_raw + NE + e);
}
__device__ __forceinline__ void load_edge(const void* ei_raw, int e, int& src, int& dst) {
    if (g_is64) {
        const long long* ei = (const long long*)ei_raw;
        src = (int)__ldg(ei + e);
        dst = (int)__ldg(ei + NE + e);
    } else {
        const int* ei = (const int*)ei_raw;
        src = __ldg(ei + e);
        dst = __ldg(ei + NE + e);
    }
}

// result unused -> REDG (no-return)
__global__ void hist_kernel(const void* __restrict__ ei_raw) {
    int e = blockIdx.x * blockDim.x + threadIdx.x;
    if (e < NE) atomicAdd(&g_deg[load_dst(ei_raw, e)], 1);
}

__global__ void scan_kernel() {
    __shared__ int part[1024];
    const int tid = threadIdx.x;
    const int CH = (NN + 1023) / 1024;  // 49
    int base = tid * CH;
    int s = 0;
#pragma unroll 4
    for (int i = 0; i < CH; i++) {
        int idx = base + i;
        if (idx < NN) s += g_deg[idx];
    }
    part[tid] = s;
    __syncthreads();
    for (int off = 1; off < 1024; off <<= 1) {
        int t = (tid >= off) ? part[tid - off] : 0;
        __syncthreads();
        part[tid] += t;
        __syncthreads();
    }
    int run = part[tid] - s;
    for (int i = 0; i < CH; i++) {
        int idx = base + i;
        if (idx < NN) {
            g_rowptr[idx] = run;
            g_cur[idx] = run;
            run += g_deg[idx];
        }
    }
    if (tid == 0) g_rowptr[NN] = NE;
}

__global__ void fill_kernel(const void* __restrict__ ei_raw) {
    int e = blockIdx.x * blockDim.x + threadIdx.x;
    if (e < NE) {
        int src, dst;
        load_edge(ei_raw, e, src, dst);
        int p = atomicAdd(&g_cur[dst], 1);
        g_esrc[p] = src;
    }
}

// ======================= helpers =======================
__device__ __forceinline__ uint32_t cvta_s(const void* p) {
    uint32_t r;
    asm("{ .reg .u64 t; cvta.to.shared.u64 t, %1; cvt.u32.u64 %0, t; }" : "=r"(r) : "l"(p));
    return r;
}
__device__ __forceinline__ uint32_t bfpack(float a, float b) {
    uint32_t r;
    asm("cvt.rn.bf16x2.f32 %0, %1, %2;" : "=r"(r) : "f"(b), "f"(a));
    return r;
}
__device__ __forceinline__ void split2(float a, float b, uint32_t& hi, uint32_t& lo) {
    hi = bfpack(a, b);
    float ah = __uint_as_float(hi << 16);
    float bh = __uint_as_float(hi & 0xFFFF0000u);
    lo = bfpack(a - ah, b - bh);
}
__device__ __forceinline__ void split4(float4 v, uint2& hi, uint2& lo) {
    split2(v.x, v.y, hi.x, lo.x);
    split2(v.z, v.w, hi.y, lo.y);
}

// ======================= CSR aggregation -> bf16 planes =======================
__global__ void agg_kernel(const float* __restrict__ x,
                           const float* __restrict__ eps,
                           char* __restrict__ aggH, char* __restrict__ aggL) {
    int node = blockIdx.x * (blockDim.x >> 5) + (threadIdx.x >> 5);
    if (node >= NN) return;
    int lane = threadIdx.x & 31;
    float s = 1.0f + __ldg(eps);
    int beg = __ldg(g_rowptr + node), end = __ldg(g_rowptr + node + 1);

    float4 a = __ldg((const float4*)(x + (size_t)node * 128) + lane);
    float4 acc = make_float4(s * a.x, s * a.y, s * a.z, s * a.w);

    int j = beg;
    for (; j + 4 <= end; j += 4) {
        int s0 = __ldg(g_esrc + j), s1 = __ldg(g_esrc + j + 1);
        int s2 = __ldg(g_esrc + j + 2), s3 = __ldg(g_esrc + j + 3);
        float4 v0 = __ldg((const float4*)(x + (size_t)s0 * 128) + lane);
        float4 v1 = __ldg((const float4*)(x + (size_t)s1 * 128) + lane);
        float4 v2 = __ldg((const float4*)(x + (size_t)s2 * 128) + lane);
        float4 v3 = __ldg((const float4*)(x + (size_t)s3 * 128) + lane);
        acc.x += v0.x + v1.x; acc.y += v0.y + v1.y;
        acc.z += v0.z + v1.z; acc.w += v0.w + v1.w;
        acc.x += v2.x + v3.x; acc.y += v2.y + v3.y;
        acc.z += v2.z + v3.z; acc.w += v2.w + v3.w;
    }
    for (; j < end; j++) {
        int s0 = __ldg(g_esrc + j);
        float4 v = __ldg((const float4*)(x + (size_t)s0 * 128) + lane);
        acc.x += v.x; acc.y += v.y; acc.z += v.z; acc.w += v.w;
    }
    uint2 hi, lo;
    split4(acc, hi, lo);
    int tile = node >> 7, r = node & 127;
    size_t bo = (size_t)tile * TBUF + ((size_t)r * AST + lane * 4) * 2;
    *(uint2*)(aggH + bo) = hi;
    *(uint2*)(aggL + bo) = lo;
}

// ===================== tensor-core MLP: register T + cp.async A prefetch =====================
#define OB_W1H 0
#define OB_W1L (OB_W1H + TBUF)
#define OB_W2H (OB_W1L + TBUF)
#define OB_W2L (OB_W2H + TBUF)
#define OB_ATH (OB_W2L + TBUF)
#define OB_ATL (OB_ATH + TBUF)
#define OB_BA  (OB_ATL + TBUF)
#define OB_BB  (OB_BA + 512)
#define MLP_SMEM (OB_BB + 512)   // 209920 B

__device__ __forceinline__ void cp16(uint32_t saddr, const void* gaddr) {
    asm volatile("cp.async.cg.shared.global [%0], [%1], 16;" :: "r"(saddr), "l"(gaddr));
}
#define CP_COMMIT() asm volatile("cp.async.commit_group;" ::: "memory")
#define CP_WAIT0()  asm volatile("cp.async.wait_group 0;" ::: "memory")

__device__ __forceinline__ void ldsm_x4(uint32_t r[4], uint32_t a) {
    asm volatile("ldmatrix.sync.aligned.m8n8.x4.shared.b16 {%0,%1,%2,%3}, [%4];"
                 : "=r"(r[0]), "=r"(r[1]), "=r"(r[2]), "=r"(r[3]) : "r"(a));
}
__device__ __forceinline__ void ldsm_x2(uint32_t r[2], uint32_t a) {
    asm volatile("ldmatrix.sync.aligned.m8n8.x2.shared.b16 {%0,%1}, [%2];"
                 : "=r"(r[0]), "=r"(r[1]) : "r"(a));
}
__device__ __forceinline__ void mma16816(float c[4], const uint32_t a[4], const uint32_t b[2]) {
    asm volatile("mma.sync.aligned.m16n8k16.row.col.f32.bf16.bf16.f32 "
                 "{%0,%1,%2,%3},{%4,%5,%6,%7},{%8,%9},{%0,%1,%2,%3};"
                 : "+f"(c[0]), "+f"(c[1]), "+f"(c[2]), "+f"(c[3])
                 : "r"(a[0]), "r"(a[1]), "r"(a[2]), "r"(a[3]), "r"(b[0]), "r"(b[1]));
}

__device__ __forceinline__ void prefetch_tile(uint32_t sb, const char* aggH, const char* aggL,
                                              int tile, int tid) {
    size_t go = (size_t)tile * TBUF;
    for (int i = tid * 16; i < TBUF; i += 256 * 16) {
        cp16(sb + OB_ATH + i, aggH + go + i);
        cp16(sb + OB_ATL + i, aggL + go + i);
    }
}

template <bool RELU_OUT>
__global__ void __launch_bounds__(256, 1)
mlp_kernel(const char* __restrict__ aggH, const char* __restrict__ aggL,
           const float* __restrict__ wA, const float* __restrict__ bA,
           const float* __restrict__ wB, const float* __restrict__ bB,
           float* __restrict__ out) {
    extern __shared__ char smem[];
    const uint32_t sb = cvta_s(smem);
    const int tid = threadIdx.x, lane = tid & 31, wid = tid >> 5;
    const int r_base = wid * 16;   // warp's 16-row band; all 128 cols
    float* ba = (float*)(smem + OB_BA);
    float* bb = (float*)(smem + OB_BB);

    // prefetch first tile while loading weights
    if (blockIdx.x < NT) prefetch_tile(sb, aggH, aggL, blockIdx.x, tid);
    CP_COMMIT();

    // Weights -> bf16 hi/lo in SMEM (row-major [c][k], stride AST)
    for (int i = tid; i < 4096; i += 256) {
        int row = i >> 5, col = (i & 31) << 2;
        uint2 hi, lo;
        float4 v = __ldg((const float4*)wA + i);
        split4(v, hi, lo);
        *(uint2*)(smem + OB_W1H + (row * AST + col) * 2) = hi;
        *(uint2*)(smem + OB_W1L + (row * AST + col) * 2) = lo;
        v = __ldg((const float4*)wB + i);
        split4(v, hi, lo);
        *(uint2*)(smem + OB_W2H + (row * AST + col) * 2) = hi;
        *(uint2*)(smem + OB_W2L + (row * AST + col) * 2) = lo;
    }
    if (tid < 128) {
        ba[tid] = __ldg(bA + tid);
        bb[tid] = __ldg(bB + tid);
    }

    const int arow = lane & 15, acol = (lane >> 4) << 3;
    const int bwrow = lane & 7, bcol = ((lane >> 3) & 1) << 3;

    for (int tile = blockIdx.x; tile < NT; tile += gridDim.x) {
        int rowBase = tile << 7;
        CP_WAIT0();
        __syncthreads();   // A tile visible to all warps (and weights on first iter)

        // ---- GEMM1: c1[n] over all 16 col-groups ----
        float c1[16][4];
#pragma unroll
        for (int n = 0; n < 16; n++)
#pragma unroll
            for (int q = 0; q < 4; q++) c1[n][q] = 0.f;
#pragma unroll
        for (int kt = 0; kt < 128; kt += 16) {
            uint32_t ah[4], al[4];
            uint32_t bo = (uint32_t)(((r_base + arow) * AST + kt + acol) * 2);
            ldsm_x4(ah, sb + OB_ATH + bo);
            ldsm_x4(al, sb + OB_ATL + bo);
#pragma unroll
            for (int n = 0; n < 16; n++) {
                uint32_t wo = (uint32_t)(((n * 8 + bwrow) * AST + kt + bcol) * 2);
                uint32_t bh[2], bl[2];
                ldsm_x2(bh, sb + OB_W1H + wo);
                ldsm_x2(bl, sb + OB_W1L + wo);
                mma16816(c1[n], ah, bh);
                mma16816(c1[n], ah, bl);
                mma16816(c1[n], al, bh);
            }
        }
        __syncthreads();   // all warps done reading A -> safe to overwrite

        // prefetch next tile's A during GEMM2/epilogues
        int nxt = tile + gridDim.x;
        if (nxt < NT) prefetch_tile(sb, aggH, aggL, nxt, tid);
        CP_COMMIT();

        // ---- epilogue1 in registers: bias+relu, split to bf16 A-fragments ----
        uint32_t tah[16][2], tal[16][2];
#pragma unroll
        for (int n = 0; n < 16; n++) {
            int col = n * 8 + ((lane & 3) << 1);
            float b0 = ba[col], b1 = ba[col + 1];
            float v0 = fmaxf(c1[n][0] + b0, 0.f);
            float v1 = fmaxf(c1[n][1] + b1, 0.f);
            float v2 = fmaxf(c1[n][2] + b0, 0.f);
            float v3 = fmaxf(c1[n][3] + b1, 0.f);
            split2(v0, v1, tah[n][0], tal[n][0]);
            split2(v2, v3, tah[n][1], tal[n][1]);
        }

        // ---- GEMM2: A-fragments from registers, W2 from SMEM ----
        float c2[16][4];
#pragma unroll
        for (int n = 0; n < 16; n++)
#pragma unroll
            for (int q = 0; q < 4; q++) c2[n][q] = 0.f;
#pragma unroll
        for (int kt = 0; kt < 8; kt++) {
            uint32_t ah[4] = { tah[2 * kt][0], tah[2 * kt][1], tah[2 * kt + 1][0], tah[2 * kt + 1][1] };
            uint32_t al[4] = { tal[2 * kt][0], tal[2 * kt][1], tal[2 * kt + 1][0], tal[2 * kt + 1][1] };
#pragma unroll
            for (int n = 0; n < 16; n++) {
                uint32_t wo = (uint32_t)(((n * 8 + bwrow) * AST + kt * 16 + bcol) * 2);
                uint32_t bh[2], bl[2];
                ldsm_x2(bh, sb + OB_W2H + wo);
                ldsm_x2(bl, sb + OB_W2L + wo);
                mma16816(c2[n], ah, bh);
                mma16816(c2[n], ah, bl);
                mma16816(c2[n], al, bh);
            }
        }

        // ---- epilogue2: bias [+relu] -> global ----
        int gr0 = rowBase + r_base + (lane >> 2);
#pragma unroll
        for (int n = 0; n < 16; n++) {
            int col = n * 8 + ((lane & 3) << 1);
            float b0 = bb[col], b1 = bb[col + 1];
            if (gr0 < NN) {
                float v0 = c2[n][0] + b0, v1 = c2[n][1] + b1;
                if (RELU_OUT) { v0 = fmaxf(v0, 0.f); v1 = fmaxf(v1, 0.f); }
                *(float2*)(out + (size_t)gr0 * 128 + col) = make_float2(v0, v1);
            }
            if (gr0 + 8 < NN) {
                float v2 = c2[n][2] + b0, v3 = c2[n][3] + b1;
                if (RELU_OUT) { v2 = fmaxf(v2, 0.f); v3 = fmaxf(v3, 0.f); }
                *(float2*)(out + (size_t)(gr0 + 8) * 128 + col) = make_float2(v2, v3);
            }
        }
    }
}

extern "C" void kernel_launch(void* const* d_in, const int* in_sizes, int n_in,
                              void* d_out, int out_size) {
    const float* features = (const float*)d_in[0];
    const void*  ei       = d_in[1];
    const float* w1a      = (const float*)d_in[2];
    const float* b1a      = (const float*)d_in[3];
    const float* w1b      = (const float*)d_in[4];
    const float* b1b      = (const float*)d_in[5];
    const float* eps1     = (const float*)d_in[6];
    const float* w2a      = (const float*)d_in[7];
    const float* b2a      = (const float*)d_in[8];
    const float* w2b      = (const float*)d_in[9];
    const float* b2b      = (const float*)d_in[10];
    const float* eps2     = (const float*)d_in[11];
    float* out = (float*)d_out;

    char *aggH, *aggL;
    float* x1;
    int* degp;
    cudaGetSymbolAddress((void**)&aggH, g_aggH);
    cudaGetSymbolAddress((void**)&aggL, g_aggL);
    cudaGetSymbolAddress((void**)&x1, g_x1);
    cudaGetSymbolAddress((void**)&degp, g_deg);

    cudaFuncSetAttribute(mlp_kernel<true>,
                         cudaFuncAttributeMaxDynamicSharedMemorySize, MLP_SMEM);
    cudaFuncSetAttribute(mlp_kernel<false>,
                         cudaFuncAttributeMaxDynamicSharedMemorySize, MLP_SMEM);

    // CSR build (once per call, reused by both layers)
    cudaMemsetAsync(degp, 0, NN * sizeof(int));
    detect_kernel<<<1, 256>>>((const int*)ei);
    hist_kernel<<<(NE + 511) / 512, 512>>>(ei);
    scan_kernel<<<1, 1024>>>();
    fill_kernel<<<(NE + 511) / 512, 512>>>(ei);

    // Layer 1
    agg_kernel<<<(NN * 32 + 255) / 256, 256>>>(features, eps1, aggH, aggL);
    mlp_kernel<true><<<148, 256, MLP_SMEM>>>(aggH, aggL, w1a, b1a, w1b, b1b, x1);

    // Layer 2
    agg_kernel<<<(NN * 32 + 255) / 256, 256>>>(x1, eps2, aggH, aggL);
    mlp_kernel<false><<<148, 256, MLP_SMEM>>>(aggH, aggL, w2a, b2a, w2b, b2b, out);
}

// round 15
// speedup vs baseline: 1.3459x; 1.0363x over previous
#include <cuda_runtime.h>
#include <cuda_fp16.h>
#include <cstdint>

#define NN 50000
#define NE 800000
#define AST 136         // bf16 elems per row: 128 data + 8 pad (272B stride)
#define NT 391          // ceil(NN/128)
#define TBUF (128 * AST * 2)   // 34816 B per 128x128 bf16 plane

// Scratch (allocation-free rule: __device__ globals)
__device__ char g_aggH[NT * TBUF];   // bf16 hi plane, tile-blocked AST layout
__device__ char g_aggL[NT * TBUF];   // bf16 lo plane
__device__ __half g_xh[NN * 128];    // fp16 gather domain: features, then x1
__device__ int g_is64;
__device__ int g_deg[NN];
__device__ int g_rowptr[NN + 1];
__device__ int g_cur[NN];
__device__ int g_esrc[NE];

// ======================= CSR build =======================
__global__ void detect_kernel(const int* __restrict__ w) {
    __shared__ int any;
    if (threadIdx.x == 0) any = 0;
    __syncthreads();
    int nz = 0;
    for (int k = threadIdx.x; k < 1024; k += blockDim.x) nz |= __ldg(w + 2 * k + 1);
    if (nz) any = 1;
    __syncthreads();
    if (threadIdx.x == 0) g_is64 = any ? 0 : 1;
}

__device__ __forceinline__ int load_dst(const void* ei_raw, int e) {
    if (g_is64) return (int)__ldg((const long long*)ei_raw + NE + e);
    return __ldg((const int*)ei_raw + NE + e);
}
__device__ __forceinline__ void load_edge(const void* ei_raw, int e, int& src, int& dst) {
    if (g_is64) {
        const long long* ei = (const long long*)ei_raw;
        src = (int)__ldg(ei + e);
        dst = (int)__ldg(ei + NE + e);
    } else {
        const int* ei = (const int*)ei_raw;
        src = __ldg(ei + e);
        dst = __ldg(ei + NE + e);
    }
}

// result unused -> REDG (no-return)
__global__ void hist_kernel(const void* __restrict__ ei_raw) {
    int e = blockIdx.x * blockDim.x + threadIdx.x;
    if (e < NE) atomicAdd(&g_deg[load_dst(ei_raw, e)], 1);
}

__global__ void scan_kernel() {
    __shared__ int part[1024];
    const int tid = threadIdx.x;
    const int CH = (NN + 1023) / 1024;  // 49
    int base = tid * CH;
    int s = 0;
#pragma unroll 4
    for (int i = 0; i < CH; i++) {
        int idx = base + i;
        if (idx < NN) s += g_deg[idx];
    }
    part[tid] = s;
    __syncthreads();
    for (int off = 1; off < 1024; off <<= 1) {
        int t = (tid >= off) ? part[tid - off] : 0;
        __syncthreads();
        part[tid] += t;
        __syncthreads();
    }
    int run = part[tid] - s;
    for (int i = 0; i < CH; i++) {
        int idx = base + i;
        if (idx < NN) {
            g_rowptr[idx] = run;
            g_cur[idx] = run;
            run += g_deg[idx];
        }
    }
    if (tid == 0) g_rowptr[NN] = NE;
}

__global__ void fill_kernel(const void* __restrict__ ei_raw) {
    int e = blockIdx.x * blockDim.x + threadIdx.x;
    if (e < NE) {
        int src, dst;
        load_edge(ei_raw, e, src, dst);
        int p = atomicAdd(&g_cur[dst], 1);
        g_esrc[p] = src;
    }
}

// ======================= helpers =======================
__device__ __forceinline__ uint32_t cvta_s(const void* p) {
    uint32_t r;
    asm("{ .reg .u64 t; cvta.to.shared.u64 t, %1; cvt.u32.u64 %0, t; }" : "=r"(r) : "l"(p));
    return r;
}
__device__ __forceinline__ uint32_t bfpack(float a, float b) {
    uint32_t r;
    asm("cvt.rn.bf16x2.f32 %0, %1, %2;" : "=r"(r) : "f"(b), "f"(a));
    return r;
}
__device__ __forceinline__ void split2(float a, float b, uint32_t& hi, uint32_t& lo) {
    hi = bfpack(a, b);
    float ah = __uint_as_float(hi << 16);
    float bh = __uint_as_float(hi & 0xFFFF0000u);
    lo = bfpack(a - ah, b - bh);
}
__device__ __forceinline__ void split4(float4 v, uint2& hi, uint2& lo) {
    split2(v.x, v.y, hi.x, lo.x);
    split2(v.z, v.w, hi.y, lo.y);
}
__device__ __forceinline__ float4 h4_to_f4(uint2 u) {
    __half2 h0 = *(__half2*)&u.x, h1 = *(__half2*)&u.y;
    float2 a = __half22float2(h0), b = __half22float2(h1);
    return make_float4(a.x, a.y, b.x, b.y);
}

// features fp32 -> fp16 plane
__global__ void tofp16_kernel(const float* __restrict__ x, __half* __restrict__ xh) {
    int i = blockIdx.x * blockDim.x + threadIdx.x;   // per 4 floats
    if (i < NN * 32) {
        float4 v = __ldg((const float4*)x + i);
        __half2 h0 = __float22half2_rn(make_float2(v.x, v.y));
        __half2 h1 = __float22half2_rn(make_float2(v.z, v.w));
        uint2 u;
        u.x = *(uint32_t*)&h0;
        u.y = *(uint32_t*)&h1;
        *(uint2*)(xh + 4 * (size_t)i) = u;
    }
}

// ======================= CSR aggregation (fp16 gather) -> bf16 planes =======================
__global__ void agg_kernel(const __half* __restrict__ xh,
                           const float* __restrict__ eps,
                           char* __restrict__ aggH, char* __restrict__ aggL) {
    int node = blockIdx.x * (blockDim.x >> 5) + (threadIdx.x >> 5);
    if (node >= NN) return;
    int lane = threadIdx.x & 31;
    float s = 1.0f + __ldg(eps);
    int beg = __ldg(g_rowptr + node), end = __ldg(g_rowptr + node + 1);

    const uint2* xr = (const uint2*)xh;  // 4 halves per uint2; 32 per row
    float4 a = h4_to_f4(__ldg(xr + (size_t)node * 32 + lane));
    float4 acc = make_float4(s * a.x, s * a.y, s * a.z, s * a.w);

    int j = beg;
    for (; j + 4 <= end; j += 4) {
        int s0 = __ldg(g_esrc + j), s1 = __ldg(g_esrc + j + 1);
        int s2 = __ldg(g_esrc + j + 2), s3 = __ldg(g_esrc + j + 3);
        float4 v0 = h4_to_f4(__ldg(xr + (size_t)s0 * 32 + lane));
        float4 v1 = h4_to_f4(__ldg(xr + (size_t)s1 * 32 + lane));
        float4 v2 = h4_to_f4(__ldg(xr + (size_t)s2 * 32 + lane));
        float4 v3 = h4_to_f4(__ldg(xr + (size_t)s3 * 32 + lane));
        acc.x += v0.x + v1.x; acc.y += v0.y + v1.y;
        acc.z += v0.z + v1.z; acc.w += v0.w + v1.w;
        acc.x += v2.x + v3.x; acc.y += v2.y + v3.y;
        acc.z += v2.z + v3.z; acc.w += v2.w + v3.w;
    }
    for (; j < end; j++) {
        int s0 = __ldg(g_esrc + j);
        float4 v = h4_to_f4(__ldg(xr + (size_t)s0 * 32 + lane));
        acc.x += v.x; acc.y += v.y; acc.z += v.z; acc.w += v.w;
    }
    uint2 hi, lo;
    split4(acc, hi, lo);
    int tile = node >> 7, r = node & 127;
    size_t bo = (size_t)tile * TBUF + ((size_t)r * AST + lane * 4) * 2;
    *(uint2*)(aggH + bo) = hi;
    *(uint2*)(aggL + bo) = lo;
}

// ===================== tensor-core MLP: register T + cp.async A prefetch =====================
#define OB_W1H 0
#define OB_W1L (OB_W1H + TBUF)
#define OB_W2H (OB_W1L + TBUF)
#define OB_W2L (OB_W2H + TBUF)
#define OB_ATH (OB_W2L + TBUF)
#define OB_ATL (OB_ATH + TBUF)
#define OB_BA  (OB_ATL + TBUF)
#define OB_BB  (OB_BA + 512)
#define MLP_SMEM (OB_BB + 512)   // 209920 B

__device__ __forceinline__ void cp16(uint32_t saddr, const void* gaddr) {
    asm volatile("cp.async.cg.shared.global [%0], [%1], 16;" :: "r"(saddr), "l"(gaddr));
}
#define CP_COMMIT() asm volatile("cp.async.commit_group;" ::: "memory")
#define CP_WAIT0()  asm volatile("cp.async.wait_group 0;" ::: "memory")

__device__ __forceinline__ void ldsm_x4(uint32_t r[4], uint32_t a) {
    asm volatile("ldmatrix.sync.aligned.m8n8.x4.shared.b16 {%0,%1,%2,%3}, [%4];"
                 : "=r"(r[0]), "=r"(r[1]), "=r"(r[2]), "=r"(r[3]) : "r"(a));
}
__device__ __forceinline__ void ldsm_x2(uint32_t r[2], uint32_t a) {
    asm volatile("ldmatrix.sync.aligned.m8n8.x2.shared.b16 {%0,%1}, [%2];"
                 : "=r"(r[0]), "=r"(r[1]) : "r"(a));
}
__device__ __forceinline__ void mma16816(float c[4], const uint32_t a[4], const uint32_t b[2]) {
    asm volatile("mma.sync.aligned.m16n8k16.row.col.f32.bf16.bf16.f32 "
                 "{%0,%1,%2,%3},{%4,%5,%6,%7},{%8,%9},{%0,%1,%2,%3};"
                 : "+f"(c[0]), "+f"(c[1]), "+f"(c[2]), "+f"(c[3])
                 : "r"(a[0]), "r"(a[1]), "r"(a[2]), "r"(a[3]), "r"(b[0]), "r"(b[1]));
}

__device__ __forceinline__ void prefetch_tile(uint32_t sb, const char* aggH, const char* aggL,
                                              int tile, int tid) {
    size_t go = (size_t)tile * TBUF;
    for (int i = tid * 16; i < TBUF; i += 256 * 16) {
        cp16(sb + OB_ATH + i, aggH + go + i);
        cp16(sb + OB_ATL + i, aggL + go + i);
    }
}

// OUT16=1: relu + write fp16 to xh16 (layer 1).  OUT16=0: write fp32 to out (layer 2).
template <int OUT16>
__global__ void __launch_bounds__(256, 1)
mlp_kernel(const char* __restrict__ aggH, const char* __restrict__ aggL,
           const float* __restrict__ wA, const float* __restrict__ bA,
           const float* __restrict__ wB, const float* __restrict__ bB,
           float* __restrict__ out, __half* __restrict__ xh16) {
    extern __shared__ char smem[];
    const uint32_t sb = cvta_s(smem);
    const int tid = threadIdx.x, lane = tid & 31, wid = tid >> 5;
    const int r_base = wid * 16;   // warp's 16-row band; all 128 cols
    float* ba = (float*)(smem + OB_BA);
    float* bb = (float*)(smem + OB_BB);

    // prefetch first tile while loading weights
    if (blockIdx.x < NT) prefetch_tile(sb, aggH, aggL, blockIdx.x, tid);
    CP_COMMIT();

    // Weights -> bf16 hi/lo in SMEM (row-major [c][k], stride AST)
    for (int i = tid; i < 4096; i += 256) {
        int row = i >> 5, col = (i & 31) << 2;
        uint2 hi, lo;
        float4 v = __ldg((const float4*)wA + i);
        split4(v, hi, lo);
        *(uint2*)(smem + OB_W1H + (row * AST + col) * 2) = hi;
        *(uint2*)(smem + OB_W1L + (row * AST + col) * 2) = lo;
        v = __ldg((const float4*)wB + i);
        split4(v, hi, lo);
        *(uint2*)(smem + OB_W2H + (row * AST + col) * 2) = hi;
        *(uint2*)(smem + OB_W2L + (row * AST + col) * 2) = lo;
    }
    if (tid < 128) {
        ba[tid] = __ldg(bA + tid);
        bb[tid] = __ldg(bB + tid);
    }

    const int arow = lane & 15, acol = (lane >> 4) << 3;
    const int bwrow = lane & 7, bcol = ((lane >> 3) & 1) << 3;

    for (int tile = blockIdx.x; tile < NT; tile += gridDim.x) {
        int rowBase = tile << 7;
        CP_WAIT0();
        __syncthreads();   // A tile visible to all warps (and weights on first iter)

        // ---- GEMM1 ----
        float c1[16][4];
#pragma unroll
        for (int n = 0; n < 16; n++)
#pragma unroll
            for (int q = 0; q < 4; q++) c1[n][q] = 0.f;
#pragma unroll
        for (int kt = 0; kt < 128; kt += 16) {
            uint32_t ah[4], al[4];
            uint32_t bo = (uint32_t)(((r_base + arow) * AST + kt + acol) * 2);
            ldsm_x4(ah, sb + OB_ATH + bo);
            ldsm_x4(al, sb + OB_ATL + bo);
#pragma unroll
            for (int n = 0; n < 16; n++) {
                uint32_t wo = (uint32_t)(((n * 8 + bwrow) * AST + kt + bcol) * 2);
                uint32_t bh[2], bl[2];
                ldsm_x2(bh, sb + OB_W1H + wo);
                ldsm_x2(bl, sb + OB_W1L + wo);
                mma16816(c1[n], ah, bh);
                mma16816(c1[n], ah, bl);
                mma16816(c1[n], al, bh);
            }
        }
        __syncthreads();   // all warps done reading A -> safe to overwrite

        // prefetch next tile's A during GEMM2/epilogues
        int nxt = tile + gridDim.x;
        if (nxt < NT) prefetch_tile(sb, aggH, aggL, nxt, tid);
        CP_COMMIT();

        // ---- epilogue1 in registers: bias+relu, split to bf16 A-fragments ----
        uint32_t tah[16][2], tal[16][2];
#pragma unroll
        for (int n = 0; n < 16; n++) {
            int col = n * 8 + ((lane & 3) << 1);
            float b0 = ba[col], b1 = ba[col + 1];
            float v0 = fmaxf(c1[n][0] + b0, 0.f);
            float v1 = fmaxf(c1[n][1] + b1, 0.f);
            float v2 = fmaxf(c1[n][2] + b0, 0.f);
            float v3 = fmaxf(c1[n][3] + b1, 0.f);
            split2(v0, v1, tah[n][0], tal[n][0]);
            split2(v2, v3, tah[n][1], tal[n][1]);
        }

        // ---- GEMM2: A-fragments from registers ----
        float c2[16][4];
#pragma unroll
        for (int n = 0; n < 16; n++)
#pragma unroll
            for (int q = 0; q < 4; q++) c2[n][q] = 0.f;
#pragma unroll
        for (int kt = 0; kt < 8; kt++) {
            uint32_t ah[4] = { tah[2 * kt][0], tah[2 * kt][1], tah[2 * kt + 1][0], tah[2 * kt + 1][1] };
            uint32_t al[4] = { tal[2 * kt][0], tal[2 * kt][1], tal[2 * kt + 1][0], tal[2 * kt + 1][1] };
#pragma unroll
            for (int n = 0; n < 16; n++) {
                uint32_t wo = (uint32_t)(((n * 8 + bwrow) * AST + kt * 16 + bcol) * 2);
                uint32_t bh[2], bl[2];
                ldsm_x2(bh, sb + OB_W2H + wo);
                ldsm_x2(bl, sb + OB_W2L + wo);
                mma16816(c2[n], ah, bh);
                mma16816(c2[n], ah, bl);
                mma16816(c2[n], al, bh);
            }
        }

        // ---- epilogue2 ----
        int gr0 = rowBase + r_base + (lane >> 2);
#pragma unroll
        for (int n = 0; n < 16; n++) {
            int col = n * 8 + ((lane & 3) << 1);
            float b0 = bb[col], b1 = bb[col + 1];
            if (gr0 < NN) {
                float v0 = c2[n][0] + b0, v1 = c2[n][1] + b1;
                if (OUT16) {
                    v0 = fmaxf(v0, 0.f); v1 = fmaxf(v1, 0.f);
                    __half2 h = __float22half2_rn(make_float2(v0, v1));
                    *(uint32_t*)(xh16 + (size_t)gr0 * 128 + col) = *(uint32_t*)&h;
                } else {
                    *(float2*)(out + (size_t)gr0 * 128 + col) = make_float2(v0, v1);
                }
            }
            if (gr0 + 8 < NN) {
                float v2 = c2[n][2] + b0, v3 = c2[n][3] + b1;
                if (OUT16) {
                    v2 = fmaxf(v2, 0.f); v3 = fmaxf(v3, 0.f);
                    __half2 h = __float22half2_rn(make_float2(v2, v3));
                    *(uint32_t*)(xh16 + (size_t)(gr0 + 8) * 128 + col) = *(uint32_t*)&h;
                } else {
                    *(float2*)(out + (size_t)(gr0 + 8) * 128 + col) = make_float2(v2, v3);
                }
            }
        }
    }
}

extern "C" void kernel_launch(void* const* d_in, const int* in_sizes, int n_in,
                              void* d_out, int out_size) {
    const float* features = (const float*)d_in[0];
    const void*  ei       = d_in[1];
    const float* w1a      = (const float*)d_in[2];
    const float* b1a      = (const float*)d_in[3];
    const float* w1b      = (const float*)d_in[4];
    const float* b1b      = (const float*)d_in[5];
    const float* eps1     = (const float*)d_in[6];
    const float* w2a      = (const float*)d_in[7];
    const float* b2a      = (const float*)d_in[8];
    const float* w2b      = (const float*)d_in[9];
    const float* b2b      = (const float*)d_in[10];
    const float* eps2     = (const float*)d_in[11];
    float* out = (float*)d_out;

    char *aggH, *aggL;
    __half* xh;
    int* degp;
    cudaGetSymbolAddress((void**)&aggH, g_aggH);
    cudaGetSymbolAddress((void**)&aggL, g_aggL);
    cudaGetSymbolAddress((void**)&xh, g_xh);
    cudaGetSymbolAddress((void**)&degp, g_deg);

    cudaFuncSetAttribute(mlp_kernel<1>,
                         cudaFuncAttributeMaxDynamicSharedMemorySize, MLP_SMEM);
    cudaFuncSetAttribute(mlp_kernel<0>,
                         cudaFuncAttributeMaxDynamicSharedMemorySize, MLP_SMEM);

    // CSR build + fp16 conversion (once per call)
    cudaMemsetAsync(degp, 0, NN * sizeof(int));
    detect_kernel<<<1, 256>>>((const int*)ei);
    tofp16_kernel<<<(NN * 32 + 255) / 256, 256>>>(features, xh);
    hist_kernel<<<(NE + 511) / 512, 512>>>(ei);
    scan_kernel<<<1, 1024>>>();
    fill_kernel<<<(NE + 511) / 512, 512>>>(ei);

    // Layer 1: agg from fp16 features; MLP1 writes x1 as fp16 (overwrites xh)
    agg_kernel<<<(NN * 32 + 255) / 256, 256>>>(xh, eps1, aggH, aggL);
    mlp_kernel<1><<<148, 256, MLP_SMEM>>>(aggH, aggL, w1a, b1a, w1b, b1b, nullptr, xh);

    // Layer 2: agg from fp16 x1; MLP2 writes fp32 out
    agg_kernel<<<(NN * 32 + 255) / 256, 256>>>(xh, eps2, aggH, aggL);
    mlp_kernel<0><<<148, 256, MLP_SMEM>>>(aggH, aggL, w2a, b2a, w2b, b2b, out, nullptr);
}

// round 16
// speedup vs baseline: 1.9720x; 1.4652x over previous
#include <cuda_runtime.h>
#include <cuda_fp16.h>
#include <cstdint>

#define NN 50000
#define NE 800000
#define AST 136         // bf16 elems per row: 128 data + 8 pad (272B stride)
#define NT 391          // ceil(NN/128)
#define TBUF (128 * AST * 2)   // 34816 B per 128x128 bf16 plane
#define NSB 49          // scan blocks: ceil(NN/1024)

// Scratch (allocation-free rule: __device__ globals)
__device__ char g_aggH[NT * TBUF];   // bf16 hi plane, tile-blocked AST layout
__device__ char g_aggL[NT * TBUF];   // bf16 lo plane
__device__ __half g_xh[NN * 128];    // fp16 gather domain: features, then x1
__device__ int g_is64;
__device__ int g_deg[NN];
__device__ int g_rowptr[NN + 1];
__device__ int g_cur[NN];
__device__ int g_esrc[NE];
__device__ int g_bsum[NSB];

// ======================= CSR build =======================
__global__ void detect_kernel(const int* __restrict__ w) {
    __shared__ int any;
    if (threadIdx.x == 0) any = 0;
    __syncthreads();
    int nz = 0;
    for (int k = threadIdx.x; k < 1024; k += blockDim.x) nz |= __ldg(w + 2 * k + 1);
    if (nz) any = 1;
    __syncthreads();
    if (threadIdx.x == 0) g_is64 = any ? 0 : 1;
}

__device__ __forceinline__ int load_dst(const void* ei_raw, int e) {
    if (g_is64) return (int)__ldg((const long long*)ei_raw + NE + e);
    return __ldg((const int*)ei_raw + NE + e);
}
__device__ __forceinline__ void load_edge(const void* ei_raw, int e, int& src, int& dst) {
    if (g_is64) {
        const long long* ei = (const long long*)ei_raw;
        src = (int)__ldg(ei + e);
        dst = (int)__ldg(ei + NE + e);
    } else {
        const int* ei = (const int*)ei_raw;
        src = __ldg(ei + e);
        dst = __ldg(ei + NE + e);
    }
}

// result unused -> REDG (no-return)
__global__ void hist_kernel(const void* __restrict__ ei_raw) {
    int e = blockIdx.x * blockDim.x + threadIdx.x;
    if (e < NE) atomicAdd(&g_deg[load_dst(ei_raw, e)], 1);
}

// ---- 3-phase parallel exclusive scan of g_deg -> g_rowptr/g_cur ----
__global__ void scan_p1() {  // grid NSB, block 1024: per-block sums
    __shared__ int red[1024];
    int idx = blockIdx.x * 1024 + threadIdx.x;
    int v = (idx < NN) ? g_deg[idx] : 0;
    red[threadIdx.x] = v;
    __syncthreads();
    for (int off = 512; off > 0; off >>= 1) {
        if (threadIdx.x < off) red[threadIdx.x] += red[threadIdx.x + off];
        __syncthreads();
    }
    if (threadIdx.x == 0) g_bsum[blockIdx.x] = red[0];
}

__global__ void scan_p2() {  // 1 thread: exclusive scan of NSB partials
    if (threadIdx.x == 0) {
        int run = 0;
        for (int i = 0; i < NSB; i++) {
            int t = g_bsum[i];
            g_bsum[i] = run;
            run += t;
        }
    }
}

__global__ void scan_p3() {  // grid NSB, block 1024: local scan + offset
    __shared__ int sc[1024];
    int idx = blockIdx.x * 1024 + threadIdx.x;
    int v = (idx < NN) ? g_deg[idx] : 0;
    sc[threadIdx.x] = v;
    __syncthreads();
    for (int off = 1; off < 1024; off <<= 1) {
        int t = (threadIdx.x >= off) ? sc[threadIdx.x - off] : 0;
        __syncthreads();
        sc[threadIdx.x] += t;
        __syncthreads();
    }
    int excl = sc[threadIdx.x] - v + g_bsum[blockIdx.x];
    if (idx < NN) {
        g_rowptr[idx] = excl;
        g_cur[idx] = excl;
    }
    if (idx == NN - 1) g_rowptr[NN] = NE;
}

__global__ void fill_kernel(const void* __restrict__ ei_raw) {
    int e = blockIdx.x * blockDim.x + threadIdx.x;
    if (e < NE) {
        int src, dst;
        load_edge(ei_raw, e, src, dst);
        int p = atomicAdd(&g_cur[dst], 1);
        g_esrc[p] = src;
    }
}

// ======================= helpers =======================
__device__ __forceinline__ uint32_t cvta_s(const void* p) {
    uint32_t r;
    asm("{ .reg .u64 t; cvta.to.shared.u64 t, %1; cvt.u32.u64 %0, t; }" : "=r"(r) : "l"(p));
    return r;
}
__device__ __forceinline__ uint32_t bfpack(float a, float b) {
    uint32_t r;
    asm("cvt.rn.bf16x2.f32 %0, %1, %2;" : "=r"(r) : "f"(b), "f"(a));
    return r;
}
__device__ __forceinline__ void split2(float a, float b, uint32_t& hi, uint32_t& lo) {
    hi = bfpack(a, b);
    float ah = __uint_as_float(hi << 16);
    float bh = __uint_as_float(hi & 0xFFFF0000u);
    lo = bfpack(a - ah, b - bh);
}
__device__ __forceinline__ void split4(float4 v, uint2& hi, uint2& lo) {
    split2(v.x, v.y, hi.x, lo.x);
    split2(v.z, v.w, hi.y, lo.y);
}
__device__ __forceinline__ float4 h4_to_f4(uint2 u) {
    __half2 h0 = *(__half2*)&u.x, h1 = *(__half2*)&u.y;
    float2 a = __half22float2(h0), b = __half22float2(h1);
    return make_float4(a.x, a.y, b.x, b.y);
}

// features fp32 -> fp16 plane
__global__ void tofp16_kernel(const float* __restrict__ x, __half* __restrict__ xh) {
    int i = blockIdx.x * blockDim.x + threadIdx.x;   // per 4 floats
    if (i < NN * 32) {
        float4 v = __ldg((const float4*)x + i);
        __half2 h0 = __float22half2_rn(make_float2(v.x, v.y));
        __half2 h1 = __float22half2_rn(make_float2(v.z, v.w));
        uint2 u;
        u.x = *(uint32_t*)&h0;
        u.y = *(uint32_t*)&h1;
        *(uint2*)(xh + 4 * (size_t)i) = u;
    }
}

// ======================= CSR aggregation (fp16 gather) -> bf16 planes =======================
__global__ void agg_kernel(const __half* __restrict__ xh,
                           const float* __restrict__ eps,
                           char* __restrict__ aggH, char* __restrict__ aggL) {
    int node = blockIdx.x * (blockDim.x >> 5) + (threadIdx.x >> 5);
    if (node >= NN) return;
    int lane = threadIdx.x & 31;
    float s = 1.0f + __ldg(eps);
    int beg = __ldg(g_rowptr + node), end = __ldg(g_rowptr + node + 1);

    const uint2* xr = (const uint2*)xh;  // 4 halves per uint2; 32 per row
    float4 a = h4_to_f4(__ldg(xr + (size_t)node * 32 + lane));
    float4 acc = make_float4(s * a.x, s * a.y, s * a.z, s * a.w);

    int j = beg;
    for (; j + 4 <= end; j += 4) {
        int s0 = __ldg(g_esrc + j), s1 = __ldg(g_esrc + j + 1);
        int s2 = __ldg(g_esrc + j + 2), s3 = __ldg(g_esrc + j + 3);
        float4 v0 = h4_to_f4(__ldg(xr + (size_t)s0 * 32 + lane));
        float4 v1 = h4_to_f4(__ldg(xr + (size_t)s1 * 32 + lane));
        float4 v2 = h4_to_f4(__ldg(xr + (size_t)s2 * 32 + lane));
        float4 v3 = h4_to_f4(__ldg(xr + (size_t)s3 * 32 + lane));
        acc.x += v0.x + v1.x; acc.y += v0.y + v1.y;
        acc.z += v0.z + v1.z; acc.w += v0.w + v1.w;
        acc.x += v2.x + v3.x; acc.y += v2.y + v3.y;
        acc.z += v2.z + v3.z; acc.w += v2.w + v3.w;
    }
    for (; j < end; j++) {
        int s0 = __ldg(g_esrc + j);
        float4 v = h4_to_f4(__ldg(xr + (size_t)s0 * 32 + lane));
        acc.x += v.x; acc.y += v.y; acc.z += v.z; acc.w += v.w;
    }
    uint2 hi, lo;
    split4(acc, hi, lo);
    int tile = node >> 7, r = node & 127;
    size_t bo = (size_t)tile * TBUF + ((size_t)r * AST + lane * 4) * 2;
    *(uint2*)(aggH + bo) = hi;
    *(uint2*)(aggL + bo) = lo;
}

// ===================== tensor-core MLP: register T + cp.async A prefetch =====================
#define OB_W1H 0
#define OB_W1L (OB_W1H + TBUF)
#define OB_W2H (OB_W1L + TBUF)
#define OB_W2L (OB_W2H + TBUF)
#define OB_ATH (OB_W2L + TBUF)
#define OB_ATL (OB_ATH + TBUF)
#define OB_BA  (OB_ATL + TBUF)
#define OB_BB  (OB_BA + 512)
#define MLP_SMEM (OB_BB + 512)   // 209920 B

__device__ __forceinline__ void cp16(uint32_t saddr, const void* gaddr) {
    asm volatile("cp.async.cg.shared.global [%0], [%1], 16;" :: "r"(saddr), "l"(gaddr));
}
#define CP_COMMIT() asm volatile("cp.async.commit_group;" ::: "memory")
#define CP_WAIT0()  asm volatile("cp.async.wait_group 0;" ::: "memory")

__device__ __forceinline__ void ldsm_x4(uint32_t r[4], uint32_t a) {
    asm volatile("ldmatrix.sync.aligned.m8n8.x4.shared.b16 {%0,%1,%2,%3}, [%4];"
                 : "=r"(r[0]), "=r"(r[1]), "=r"(r[2]), "=r"(r[3]) : "r"(a));
}
__device__ __forceinline__ void ldsm_x2(uint32_t r[2], uint32_t a) {
    asm volatile("ldmatrix.sync.aligned.m8n8.x2.shared.b16 {%0,%1}, [%2];"
                 : "=r"(r[0]), "=r"(r[1]) : "r"(a));
}
__device__ __forceinline__ void mma16816(float c[4], const uint32_t a[4], const uint32_t b[2]) {
    asm volatile("mma.sync.aligned.m16n8k16.row.col.f32.bf16.bf16.f32 "
                 "{%0,%1,%2,%3},{%4,%5,%6,%7},{%8,%9},{%0,%1,%2,%3};"
                 : "+f"(c[0]), "+f"(c[1]), "+f"(c[2]), "+f"(c[3])
                 : "r"(a[0]), "r"(a[1]), "r"(a[2]), "r"(a[3]), "r"(b[0]), "r"(b[1]));
}

__device__ __forceinline__ void prefetch_tile(uint32_t sb, const char* aggH, const char* aggL,
                                              int tile, int tid) {
    size_t go = (size_t)tile * TBUF;
    for (int i = tid * 16; i < TBUF; i += 256 * 16) {
        cp16(sb + OB_ATH + i, aggH + go + i);
        cp16(sb + OB_ATL + i, aggL + go + i);
    }
}

// OUT16=1: relu + write fp16 to xh16 (layer 1).  OUT16=0: write fp32 to out (layer 2).
template <int OUT16>
__global__ void __launch_bounds__(256, 1)
mlp_kernel(const char* __restrict__ aggH, const char* __restrict__ aggL,
           const float* __restrict__ wA, const float* __restrict__ bA,
           const float* __restrict__ wB, const float* __restrict__ bB,
           float* __restrict__ out, __half* __restrict__ xh16) {
    extern __shared__ char smem[];
    const uint32_t sb = cvta_s(smem);
    const int tid = threadIdx.x, lane = tid & 31, wid = tid >> 5;
    const int r_base = wid * 16;   // warp's 16-row band; all 128 cols
    float* ba = (float*)(smem + OB_BA);
    float* bb = (float*)(smem + OB_BB);

    // prefetch first tile while loading weights
    if (blockIdx.x < NT) prefetch_tile(sb, aggH, aggL, blockIdx.x, tid);
    CP_COMMIT();

    // Weights -> bf16 hi/lo in SMEM (row-major [c][k], stride AST)
    for (int i = tid; i < 4096; i += 256) {
        int row = i >> 5, col = (i & 31) << 2;
        uint2 hi, lo;
        float4 v = __ldg((const float4*)wA + i);
        split4(v, hi, lo);
        *(uint2*)(smem + OB_W1H + (row * AST + col) * 2) = hi;
        *(uint2*)(smem + OB_W1L + (row * AST + col) * 2) = lo;
        v = __ldg((const float4*)wB + i);
        split4(v, hi, lo);
        *(uint2*)(smem + OB_W2H + (row * AST + col) * 2) = hi;
        *(uint2*)(smem + OB_W2L + (row * AST + col) * 2) = lo;
    }
    if (tid < 128) {
        ba[tid] = __ldg(bA + tid);
        bb[tid] = __ldg(bB + tid);
    }

    const int arow = lane & 15, acol = (lane >> 4) << 3;
    const int bwrow = lane & 7, bcol = ((lane >> 3) & 1) << 3;

    for (int tile = blockIdx.x; tile < NT; tile += gridDim.x) {
        int rowBase = tile << 7;
        CP_WAIT0();
        __syncthreads();   // A tile visible to all warps (and weights on first iter)

        // ---- GEMM1 ----
        float c1[16][4];
#pragma unroll
        for (int n = 0; n < 16; n++)
#pragma unroll
            for (int q = 0; q < 4; q++) c1[n][q] = 0.f;
#pragma unroll
        for (int kt = 0; kt < 128; kt += 16) {
            uint32_t ah[4], al[4];
            uint32_t bo = (uint32_t)(((r_base + arow) * AST + kt + acol) * 2);
            ldsm_x4(ah, sb + OB_ATH + bo);
            ldsm_x4(al, sb + OB_ATL + bo);
#pragma unroll
            for (int n = 0; n < 16; n++) {
                uint32_t wo = (uint32_t)(((n * 8 + bwrow) * AST + kt + bcol) * 2);
                uint32_t bh[2], bl[2];
                ldsm_x2(bh, sb + OB_W1H + wo);
                ldsm_x2(bl, sb + OB_W1L + wo);
                mma16816(c1[n], ah, bh);
                mma16816(c1[n], ah, bl);
                mma16816(c1[n], al, bh);
            }
        }
        __syncthreads();   // all warps done reading A -> safe to overwrite

        // prefetch next tile's A during GEMM2/epilogues
        int nxt = tile + gridDim.x;
        if (nxt < NT) prefetch_tile(sb, aggH, aggL, nxt, tid);
        CP_COMMIT();

        // ---- epilogue1 in registers: bias+relu, split to bf16 A-fragments ----
        uint32_t tah[16][2], tal[16][2];
#pragma unroll
        for (int n = 0; n < 16; n++) {
            int col = n * 8 + ((lane & 3) << 1);
            float b0 = ba[col], b1 = ba[col + 1];
            float v0 = fmaxf(c1[n][0] + b0, 0.f);
            float v1 = fmaxf(c1[n][1] + b1, 0.f);
            float v2 = fmaxf(c1[n][2] + b0, 0.f);
            float v3 = fmaxf(c1[n][3] + b1, 0.f);
            split2(v0, v1, tah[n][0], tal[n][0]);
            split2(v2, v3, tah[n][1], tal[n][1]);
        }

        // ---- GEMM2: A-fragments from registers ----
        float c2[16][4];
#pragma unroll
        for (int n = 0; n < 16; n++)
#pragma unroll
            for (int q = 0; q < 4; q++) c2[n][q] = 0.f;
#pragma unroll
        for (int kt = 0; kt < 8; kt++) {
            uint32_t ah[4] = { tah[2 * kt][0], tah[2 * kt][1], tah[2 * kt + 1][0], tah[2 * kt + 1][1] };
            uint32_t al[4] = { tal[2 * kt][0], tal[2 * kt][1], tal[2 * kt + 1][0], tal[2 * kt + 1][1] };
#pragma unroll
            for (int n = 0; n < 16; n++) {
                uint32_t wo = (uint32_t)(((n * 8 + bwrow) * AST + kt * 16 + bcol) * 2);
                uint32_t bh[2], bl[2];
                ldsm_x2(bh, sb + OB_W2H + wo);
                ldsm_x2(bl, sb + OB_W2L + wo);
                mma16816(c2[n], ah, bh);
                mma16816(c2[n], ah, bl);
                mma16816(c2[n], al, bh);
            }
        }

        // ---- epilogue2 ----
        int gr0 = rowBase + r_base + (lane >> 2);
#pragma unroll
        for (int n = 0; n < 16; n++) {
            int col = n * 8 + ((lane & 3) << 1);
            float b0 = bb[col], b1 = bb[col + 1];
            if (gr0 < NN) {
                float v0 = c2[n][0] + b0, v1 = c2[n][1] + b1;
                if (OUT16) {
                    v0 = fmaxf(v0, 0.f); v1 = fmaxf(v1, 0.f);
                    __half2 h = __float22half2_rn(make_float2(v0, v1));
                    *(uint32_t*)(xh16 + (size_t)gr0 * 128 + col) = *(uint32_t*)&h;
                } else {
                    *(float2*)(out + (size_t)gr0 * 128 + col) = make_float2(v0, v1);
                }
            }
            if (gr0 + 8 < NN) {
                float v2 = c2[n][2] + b0, v3 = c2[n][3] + b1;
                if (OUT16) {
                    v2 = fmaxf(v2, 0.f); v3 = fmaxf(v3, 0.f);
                    __half2 h = __float22half2_rn(make_float2(v2, v3));
                    *(uint32_t*)(xh16 + (size_t)(gr0 + 8) * 128 + col) = *(uint32_t*)&h;
                } else {
                    *(float2*)(out + (size_t)(gr0 + 8) * 128 + col) = make_float2(v2, v3);
                }
            }
        }
    }
}

extern "C" void kernel_launch(void* const* d_in, const int* in_sizes, int n_in,
                              void* d_out, int out_size) {
    const float* features = (const float*)d_in[0];
    const void*  ei       = d_in[1];
    const float* w1a      = (const float*)d_in[2];
    const float* b1a      = (const float*)d_in[3];
    const float* w1b      = (const float*)d_in[4];
    const float* b1b      = (const float*)d_in[5];
    const float* eps1     = (const float*)d_in[6];
    const float* w2a      = (const float*)d_in[7];
    const float* b2a      = (const float*)d_in[8];
    const float* w2b      = (const float*)d_in[9];
    const float* b2b      = (const float*)d_in[10];
    const float* eps2     = (const float*)d_in[11];
    float* out = (float*)d_out;

    char *aggH, *aggL;
    __half* xh;
    int* degp;
    cudaGetSymbolAddress((void**)&aggH, g_aggH);
    cudaGetSymbolAddress((void**)&aggL, g_aggL);
    cudaGetSymbolAddress((void**)&xh, g_xh);
    cudaGetSymbolAddress((void**)&degp, g_deg);

    cudaFuncSetAttribute(mlp_kernel<1>,
                         cudaFuncAttributeMaxDynamicSharedMemorySize, MLP_SMEM);
    cudaFuncSetAttribute(mlp_kernel<0>,
                         cudaFuncAttributeMaxDynamicSharedMemorySize, MLP_SMEM);

    // CSR build + fp16 conversion (once per call)
    cudaMemsetAsync(degp, 0, NN * sizeof(int));
    detect_kernel<<<1, 256>>>((const int*)ei);
    tofp16_kernel<<<(NN * 32 + 255) / 256, 256>>>(features, xh);
    hist_kernel<<<(NE + 511) / 512, 512>>>(ei);
    scan_p1<<<NSB, 1024>>>();
    scan_p2<<<1, 32>>>();
    scan_p3<<<NSB, 1024>>>();
    fill_kernel<<<(NE + 511) / 512, 512>>>(ei);

    // Layer 1: agg from fp16 features; MLP1 writes x1 as fp16 (overwrites xh)
    agg_kernel<<<(NN * 32 + 255) / 256, 256>>>(xh, eps1, aggH, aggL);
    mlp_kernel<1><<<148, 256, MLP_SMEM>>>(aggH, aggL, w1a, b1a, w1b, b1b, nullptr, xh);

    // Layer 2: agg from fp16 x1; MLP2 writes fp32 out
    agg_kernel<<<(NN * 32 + 255) / 256, 256>>>(xh, eps2, aggH, aggL);
    mlp_kernel<0><<<148, 256, MLP_SMEM>>>(aggH, aggL, w2a, b2a, w2b, b2b, out, nullptr);
}

// round 17
// speedup vs baseline: 2.0258x; 1.0273x over previous
#include <cuda_runtime.h>
#include <cuda_fp16.h>
#include <cstdint>

#define NN 50000
#define NE 800000
#define AST 136         // bf16 elems per row: 128 data + 8 pad (272B stride)
#define NT 391          // ceil(NN/128)
#define TBUF (128 * AST * 2)   // 34816 B per 128x128 bf16 plane
#define NSB 49          // scan blocks: ceil(NN/1024)
#define HB 1563         // hist blocks (512 thr)
#define CB 3125         // tofp16 blocks (512 thr, 4 floats/thread)

// Scratch (allocation-free rule: __device__ globals)
__device__ char g_aggH[NT * TBUF];   // bf16 hi plane, tile-blocked AST layout
__device__ char g_aggL[NT * TBUF];   // bf16 lo plane
__device__ __half g_xh[NN * 128];    // fp16 gather domain: features, then x1
__device__ int g_is64;
__device__ int g_deg[NN];
__device__ int g_rowptr[NN + 1];
__device__ int g_cur[NN];
__device__ int g_esrc[NE];
__device__ int g_bsum[NSB];

// ======================= CSR build =======================
// zero deg everywhere; block 0 also detects edge dtype
__global__ void detect_and_zero_kernel(const int* __restrict__ w) {
    int i = blockIdx.x * blockDim.x + threadIdx.x;
    for (int k = i; k < NN; k += gridDim.x * blockDim.x) g_deg[k] = 0;
    if (blockIdx.x == 0) {
        __shared__ int any;
        if (threadIdx.x == 0) any = 0;
        __syncthreads();
        int nz = 0;
        for (int k = threadIdx.x; k < 1024; k += blockDim.x) nz |= __ldg(w + 2 * k + 1);
        if (nz) any = 1;
        __syncthreads();
        if (threadIdx.x == 0) g_is64 = any ? 0 : 1;
    }
}

__device__ __forceinline__ int load_dst(const void* ei_raw, int e) {
    if (g_is64) return (int)__ldg((const long long*)ei_raw + NE + e);
    return __ldg((const int*)ei_raw + NE + e);
}
__device__ __forceinline__ void load_edge(const void* ei_raw, int e, int& src, int& dst) {
    if (g_is64) {
        const long long* ei = (const long long*)ei_raw;
        src = (int)__ldg(ei + e);
        dst = (int)__ldg(ei + NE + e);
    } else {
        const int* ei = (const int*)ei_raw;
        src = __ldg(ei + e);
        dst = __ldg(ei + NE + e);
    }
}

// fused: blocks [0,HB) histogram edges (REDG); blocks [HB,HB+CB) convert features->fp16
__global__ void hist_tofp16_kernel(const void* __restrict__ ei_raw,
                                   const float* __restrict__ x,
                                   __half* __restrict__ xh) {
    if (blockIdx.x < HB) {
        int e = blockIdx.x * 512 + threadIdx.x;
        if (e < NE) atomicAdd(&g_deg[load_dst(ei_raw, e)], 1);
    } else {
        int i = (blockIdx.x - HB) * 512 + threadIdx.x;   // per 4 floats
        if (i < NN * 32) {
            float4 v = __ldg((const float4*)x + i);
            __half2 h0 = __float22half2_rn(make_float2(v.x, v.y));
            __half2 h1 = __float22half2_rn(make_float2(v.z, v.w));
            uint2 u;
            u.x = *(uint32_t*)&h0;
            u.y = *(uint32_t*)&h1;
            *(uint2*)(xh + 4 * (size_t)i) = u;
        }
    }
}

// ---- 2-phase parallel exclusive scan of g_deg -> g_rowptr/g_cur ----
__global__ void scan_p1() {  // grid NSB, block 1024: per-block sums
    __shared__ int red[1024];
    int idx = blockIdx.x * 1024 + threadIdx.x;
    int v = (idx < NN) ? g_deg[idx] : 0;
    red[threadIdx.x] = v;
    __syncthreads();
    for (int off = 512; off > 0; off >>= 1) {
        if (threadIdx.x < off) red[threadIdx.x] += red[threadIdx.x + off];
        __syncthreads();
    }
    if (threadIdx.x == 0) g_bsum[blockIdx.x] = red[0];
}

__global__ void scan_p3() {  // grid NSB, block 1024: inline bsum scan + local scan + offset
    __shared__ int sc[1024];
    __shared__ int bs[64];
    // each block redundantly computes the exclusive prefix of bsum
    if (threadIdx.x < 64)
        bs[threadIdx.x] = (threadIdx.x < NSB) ? g_bsum[threadIdx.x] : 0;
    __syncthreads();
    int own = (threadIdx.x < 64) ? bs[threadIdx.x] : 0;
    for (int off = 1; off < 64; off <<= 1) {
        int t = (threadIdx.x >= off && threadIdx.x < 64) ? bs[threadIdx.x - off] : 0;
        __syncthreads();
        if (threadIdx.x < 64) bs[threadIdx.x] += t;
        __syncthreads();
    }
    if (threadIdx.x < 64) bs[threadIdx.x] -= own;  // exclusive
    __syncthreads();

    int idx = blockIdx.x * 1024 + threadIdx.x;
    int v = (idx < NN) ? g_deg[idx] : 0;
    sc[threadIdx.x] = v;
    __syncthreads();
    for (int off = 1; off < 1024; off <<= 1) {
        int t = (threadIdx.x >= off) ? sc[threadIdx.x - off] : 0;
        __syncthreads();
        sc[threadIdx.x] += t;
        __syncthreads();
    }
    int excl = sc[threadIdx.x] - v + bs[blockIdx.x];
    if (idx < NN) {
        g_rowptr[idx] = excl;
        g_cur[idx] = excl;
    }
    if (idx == NN - 1) g_rowptr[NN] = NE;
}

__global__ void fill_kernel(const void* __restrict__ ei_raw) {
    int e = blockIdx.x * blockDim.x + threadIdx.x;
    if (e < NE) {
        int src, dst;
        load_edge(ei_raw, e, src, dst);
        int p = atomicAdd(&g_cur[dst], 1);
        g_esrc[p] = src;
    }
}

// ======================= helpers =======================
__device__ __forceinline__ uint32_t cvta_s(const void* p) {
    uint32_t r;
    asm("{ .reg .u64 t; cvta.to.shared.u64 t, %1; cvt.u32.u64 %0, t; }" : "=r"(r) : "l"(p));
    return r;
}
__device__ __forceinline__ uint32_t bfpack(float a, float b) {
    uint32_t r;
    asm("cvt.rn.bf16x2.f32 %0, %1, %2;" : "=r"(r) : "f"(b), "f"(a));
    return r;
}
__device__ __forceinline__ void split2(float a, float b, uint32_t& hi, uint32_t& lo) {
    hi = bfpack(a, b);
    float ah = __uint_as_float(hi << 16);
    float bh = __uint_as_float(hi & 0xFFFF0000u);
    lo = bfpack(a - ah, b - bh);
}
__device__ __forceinline__ void split4(float4 v, uint2& hi, uint2& lo) {
    split2(v.x, v.y, hi.x, lo.x);
    split2(v.z, v.w, hi.y, lo.y);
}
__device__ __forceinline__ float4 h4_to_f4(uint2 u) {
    __half2 h0 = *(__half2*)&u.x, h1 = *(__half2*)&u.y;
    float2 a = __half22float2(h0), b = __half22float2(h1);
    return make_float4(a.x, a.y, b.x, b.y);
}

// ======================= CSR aggregation (fp16 gather) -> bf16 planes =======================
__global__ void agg_kernel(const __half* __restrict__ xh,
                           const float* __restrict__ eps,
                           char* __restrict__ aggH, char* __restrict__ aggL) {
    int node = blockIdx.x * (blockDim.x >> 5) + (threadIdx.x >> 5);
    if (node >= NN) return;
    int lane = threadIdx.x & 31;
    float s = 1.0f + __ldg(eps);
    int beg = __ldg(g_rowptr + node), end = __ldg(g_rowptr + node + 1);

    const uint2* xr = (const uint2*)xh;  // 4 halves per uint2; 32 per row
    float4 a = h4_to_f4(__ldg(xr + (size_t)node * 32 + lane));
    float4 acc = make_float4(s * a.x, s * a.y, s * a.z, s * a.w);

    int j = beg;
    for (; j + 4 <= end; j += 4) {
        int s0 = __ldg(g_esrc + j), s1 = __ldg(g_esrc + j + 1);
        int s2 = __ldg(g_esrc + j + 2), s3 = __ldg(g_esrc + j + 3);
        float4 v0 = h4_to_f4(__ldg(xr + (size_t)s0 * 32 + lane));
        float4 v1 = h4_to_f4(__ldg(xr + (size_t)s1 * 32 + lane));
        float4 v2 = h4_to_f4(__ldg(xr + (size_t)s2 * 32 + lane));
        float4 v3 = h4_to_f4(__ldg(xr + (size_t)s3 * 32 + lane));
        acc.x += v0.x + v1.x; acc.y += v0.y + v1.y;
        acc.z += v0.z + v1.z; acc.w += v0.w + v1.w;
        acc.x += v2.x + v3.x; acc.y += v2.y + v3.y;
        acc.z += v2.z + v3.z; acc.w += v2.w + v3.w;
    }
    for (; j < end; j++) {
        int s0 = __ldg(g_esrc + j);
        float4 v = h4_to_f4(__ldg(xr + (size_t)s0 * 32 + lane));
        acc.x += v.x; acc.y += v.y; acc.z += v.z; acc.w += v.w;
    }
    uint2 hi, lo;
    split4(acc, hi, lo);
    int tile = node >> 7, r = node & 127;
    size_t bo = (size_t)tile * TBUF + ((size_t)r * AST + lane * 4) * 2;
    *(uint2*)(aggH + bo) = hi;
    *(uint2*)(aggL + bo) = lo;
}

// ===================== tensor-core MLP: register T + cp.async A prefetch =====================
#define OB_W1H 0
#define OB_W1L (OB_W1H + TBUF)
#define OB_W2H (OB_W1L + TBUF)
#define OB_W2L (OB_W2H + TBUF)
#define OB_ATH (OB_W2L + TBUF)
#define OB_ATL (OB_ATH + TBUF)
#define OB_BA  (OB_ATL + TBUF)
#define OB_BB  (OB_BA + 512)
#define MLP_SMEM (OB_BB + 512)   // 209920 B

__device__ __forceinline__ void cp16(uint32_t saddr, const void* gaddr) {
    asm volatile("cp.async.cg.shared.global [%0], [%1], 16;" :: "r"(saddr), "l"(gaddr));
}
#define CP_COMMIT() asm volatile("cp.async.commit_group;" ::: "memory")
#define CP_WAIT0()  asm volatile("cp.async.wait_group 0;" ::: "memory")

__device__ __forceinline__ void ldsm_x4(uint32_t r[4], uint32_t a) {
    asm volatile("ldmatrix.sync.aligned.m8n8.x4.shared.b16 {%0,%1,%2,%3}, [%4];"
                 : "=r"(r[0]), "=r"(r[1]), "=r"(r[2]), "=r"(r[3]) : "r"(a));
}
__device__ __forceinline__ void ldsm_x2(uint32_t r[2], uint32_t a) {
    asm volatile("ldmatrix.sync.aligned.m8n8.x2.shared.b16 {%0,%1}, [%2];"
                 : "=r"(r[0]), "=r"(r[1]) : "r"(a));
}
__device__ __forceinline__ void mma16816(float c[4], const uint32_t a[4], const uint32_t b[2]) {
    asm volatile("mma.sync.aligned.m16n8k16.row.col.f32.bf16.bf16.f32 "
                 "{%0,%1,%2,%3},{%4,%5,%6,%7},{%8,%9},{%0,%1,%2,%3};"
                 : "+f"(c[0]), "+f"(c[1]), "+f"(c[2]), "+f"(c[3])
                 : "r"(a[0]), "r"(a[1]), "r"(a[2]), "r"(a[3]), "r"(b[0]), "r"(b[1]));
}

__device__ __forceinline__ void prefetch_tile(uint32_t sb, const char* aggH, const char* aggL,
                                              int tile, int tid) {
    size_t go = (size_t)tile * TBUF;
    for (int i = tid * 16; i < TBUF; i += 256 * 16) {
        cp16(sb + OB_ATH + i, aggH + go + i);
        cp16(sb + OB_ATL + i, aggL + go + i);
    }
}

// OUT16=1: relu + write fp16 to xh16 (layer 1).  OUT16=0: write fp32 to out (layer 2).
template <int OUT16>
__global__ void __launch_bounds__(256, 1)
mlp_kernel(const char* __restrict__ aggH, const char* __restrict__ aggL,
           const float* __restrict__ wA, const float* __restrict__ bA,
           const float* __restrict__ wB, const float* __restrict__ bB,
           float* __restrict__ out, __half* __restrict__ xh16) {
    extern __shared__ char smem[];
    const uint32_t sb = cvta_s(smem);
    const int tid = threadIdx.x, lane = tid & 31, wid = tid >> 5;
    const int r_base = wid * 16;   // warp's 16-row band; all 128 cols
    float* ba = (float*)(smem + OB_BA);
    float* bb = (float*)(smem + OB_BB);

    // prefetch first tile while loading weights
    if (blockIdx.x < NT) prefetch_tile(sb, aggH, aggL, blockIdx.x, tid);
    CP_COMMIT();

    // Weights -> bf16 hi/lo in SMEM (row-major [c][k], stride AST)
    for (int i = tid; i < 4096; i += 256) {
        int row = i >> 5, col = (i & 31) << 2;
        uint2 hi, lo;
        float4 v = __ldg((const float4*)wA + i);
        split4(v, hi, lo);
        *(uint2*)(smem + OB_W1H + (row * AST + col) * 2) = hi;
        *(uint2*)(smem + OB_W1L + (row * AST + col) * 2) = lo;
        v = __ldg((const float4*)wB + i);
        split4(v, hi, lo);
        *(uint2*)(smem + OB_W2H + (row * AST + col) * 2) = hi;
        *(uint2*)(smem + OB_W2L + (row * AST + col) * 2) = lo;
    }
    if (tid < 128) {
        ba[tid] = __ldg(bA + tid);
        bb[tid] = __ldg(bB + tid);
    }

    const int arow = lane & 15, acol = (lane >> 4) << 3;
    const int bwrow = lane & 7, bcol = ((lane >> 3) & 1) << 3;

    for (int tile = blockIdx.x; tile < NT; tile += gridDim.x) {
        int rowBase = tile << 7;
        CP_WAIT0();
        __syncthreads();   // A tile visible to all warps (and weights on first iter)

        // ---- GEMM1 ----
        float c1[16][4];
#pragma unroll
        for (int n = 0; n < 16; n++)
#pragma unroll
            for (int q = 0; q < 4; q++) c1[n][q] = 0.f;
#pragma unroll
        for (int kt = 0; kt < 128; kt += 16) {
            uint32_t ah[4], al[4];
            uint32_t bo = (uint32_t)(((r_base + arow) * AST + kt + acol) * 2);
            ldsm_x4(ah, sb + OB_ATH + bo);
            ldsm_x4(al, sb + OB_ATL + bo);
#pragma unroll
            for (int n = 0; n < 16; n++) {
                uint32_t wo = (uint32_t)(((n * 8 + bwrow) * AST + kt + bcol) * 2);
                uint32_t bh[2], bl[2];
                ldsm_x2(bh, sb + OB_W1H + wo);
                ldsm_x2(bl, sb + OB_W1L + wo);
                mma16816(c1[n], ah, bh);
                mma16816(c1[n], ah, bl);
                mma16816(c1[n], al, bh);
            }
        }
        __syncthreads();   // all warps done reading A -> safe to overwrite

        // prefetch next tile's A during GEMM2/epilogues
        int nxt = tile + gridDim.x;
        if (nxt < NT) prefetch_tile(sb, aggH, aggL, nxt, tid);
        CP_COMMIT();

        // ---- epilogue1 in registers: bias+relu, split to bf16 A-fragments ----
        uint32_t tah[16][2], tal[16][2];
#pragma unroll
        for (int n = 0; n < 16; n++) {
            int col = n * 8 + ((lane & 3) << 1);
            float b0 = ba[col], b1 = ba[col + 1];
            float v0 = fmaxf(c1[n][0] + b0, 0.f);
            float v1 = fmaxf(c1[n][1] + b1, 0.f);
            float v2 = fmaxf(c1[n][2] + b0, 0.f);
            float v3 = fmaxf(c1[n][3] + b1, 0.f);
            split2(v0, v1, tah[n][0], tal[n][0]);
            split2(v2, v3, tah[n][1], tal[n][1]);
        }

        // ---- GEMM2: A-fragments from registers ----
        float c2[16][4];
#pragma unroll
        for (int n = 0; n < 16; n++)
#pragma unroll
            for (int q = 0; q < 4; q++) c2[n][q] = 0.f;
#pragma unroll
        for (int kt = 0; kt < 8; kt++) {
            uint32_t ah[4] = { tah[2 * kt][0], tah[2 * kt][1], tah[2 * kt + 1][0], tah[2 * kt + 1][1] };
            uint32_t al[4] = { tal[2 * kt][0], tal[2 * kt][1], tal[2 * kt + 1][0], tal[2 * kt + 1][1] };
#pragma unroll
            for (int n = 0; n < 16; n++) {
                uint32_t wo = (uint32_t)(((n * 8 + bwrow) * AST + kt * 16 + bcol) * 2);
                uint32_t bh[2], bl[2];
                ldsm_x2(bh, sb + OB_W2H + wo);
                ldsm_x2(bl, sb + OB_W2L + wo);
                mma16816(c2[n], ah, bh);
                mma16816(c2[n], ah, bl);
                mma16816(c2[n], al, bh);
            }
        }

        // ---- epilogue2 ----
        int gr0 = rowBase + r_base + (lane >> 2);
#pragma unroll
        for (int n = 0; n < 16; n++) {
            int col = n * 8 + ((lane & 3) << 1);
            float b0 = bb[col], b1 = bb[col + 1];
            if (gr0 < NN) {
                float v0 = c2[n][0] + b0, v1 = c2[n][1] + b1;
                if (OUT16) {
                    v0 = fmaxf(v0, 0.f); v1 = fmaxf(v1, 0.f);
                    __half2 h = __float22half2_rn(make_float2(v0, v1));
                    *(uint32_t*)(xh16 + (size_t)gr0 * 128 + col) = *(uint32_t*)&h;
                } else {
                    *(float2*)(out + (size_t)gr0 * 128 + col) = make_float2(v0, v1);
                }
            }
            if (gr0 + 8 < NN) {
                float v2 = c2[n][2] + b0, v3 = c2[n][3] + b1;
                if (OUT16) {
                    v2 = fmaxf(v2, 0.f); v3 = fmaxf(v3, 0.f);
                    __half2 h = __float22half2_rn(make_float2(v2, v3));
                    *(uint32_t*)(xh16 + (size_t)(gr0 + 8) * 128 + col) = *(uint32_t*)&h;
                } else {
                    *(float2*)(out + (size_t)(gr0 + 8) * 128 + col) = make_float2(v2, v3);
                }
            }
        }
    }
}

extern "C" void kernel_launch(void* const* d_in, const int* in_sizes, int n_in,
                              void* d_out, int out_size) {
    const float* features = (const float*)d_in[0];
    const void*  ei       = d_in[1];
    const float* w1a      = (const float*)d_in[2];
    const float* b1a      = (const float*)d_in[3];
    const float* w1b      = (const float*)d_in[4];
    const float* b1b      = (const float*)d_in[5];
    const float* eps1     = (const float*)d_in[6];
    const float* w2a      = (const float*)d_in[7];
    const float* b2a      = (const float*)d_in[8];
    const float* w2b      = (const float*)d_in[9];
    const float* b2b      = (const float*)d_in[10];
    const float* eps2     = (const float*)d_in[11];
    float* out = (float*)d_out;

    char *aggH, *aggL;
    __half* xh;
    cudaGetSymbolAddress((void**)&aggH, g_aggH);
    cudaGetSymbolAddress((void**)&aggL, g_aggL);
    cudaGetSymbolAddress((void**)&xh, g_xh);

    cudaFuncSetAttribute(mlp_kernel<1>,
                         cudaFuncAttributeMaxDynamicSharedMemorySize, MLP_SMEM);
    cudaFuncSetAttribute(mlp_kernel<0>,
                         cudaFuncAttributeMaxDynamicSharedMemorySize, MLP_SMEM);

    // CSR build + fp16 conversion (once per call)
    detect_and_zero_kernel<<<64, 256>>>((const int*)ei);
    hist_tofp16_kernel<<<HB + CB, 512>>>(ei, features, xh);
    scan_p1<<<NSB, 1024>>>();
    scan_p3<<<NSB, 1024>>>();
    fill_kernel<<<(NE + 511) / 512, 512>>>(ei);

    // Layer 1: agg from fp16 features; MLP1 writes x1 as fp16 (overwrites xh)
    agg_kernel<<<(NN * 32 + 255) / 256, 256>>>(xh, eps1, aggH, aggL);
    mlp_kernel<1><<<148, 256, MLP_SMEM>>>(aggH, aggL, w1a, b1a, w1b, b1b, nullptr, xh);

    // Layer 2: agg from fp16 x1; MLP2 writes fp32 out
    agg_kernel<<<(NN * 32 + 255) / 256, 256>>>(xh, eps2, aggH, aggL);
    mlp_kernel<0><<<148, 256, MLP_SMEM>>>(aggH, aggL, w2a, b2a, w2b, b2b, out, nullptr);
}